// round 12
// baseline (speedup 1.0000x reference)
#include <cuda_runtime.h>
#include <cuda_fp16.h>
#include <math.h>
#include <stdint.h>

// ---------------- problem constants ----------------
#define B_    16
#define NTOK  196
#define SPLN  98
#define N_    491          // 1 + 98*4 + 98
#define C_    768
#define HM_   3072
#define H_    12
#define D_    64
#define L_    4
#define M_ROWS (B_*N_)     // 7856

// weight sizes
#define SW_SZ   (C_*4*C_)
#define QW_SZ   (C_*3*C_)
#define PW_SZ   (C_*C_)
#define F1_SZ   (C_*HM_)
#define F2_SZ   (HM_*C_)

#define PERSIST_CTAS 296

// ---------------- device scratch ----------------
__device__ float  g_x   [B_*N_*C_];
__device__ __half g_h   [B_*N_*C_];
__device__ __half g_qkv [B_*N_*3*C_];
__device__ __half g_o   [B_*N_*C_];
__device__ __half g_mlp [B_*N_*HM_];
__device__ __half g_tok [B_*SPLN*C_];
__device__ int    g_ord [B_*NTOK];
__device__ float  g_glb [B_*(N_-1)];
__device__ float  g_cls [B_*(N_-1)];
__device__ float  g_srow[B_*H_*512];
// fp16 weights
__device__ __half g_wsplit[SW_SZ];
__device__ __half g_wqkv  [L_*QW_SZ];
__device__ __half g_wproj [L_*PW_SZ];
__device__ __half g_wfc1  [L_*F1_SZ];
__device__ __half g_wfc2  [L_*F2_SZ];

// ---------------- helpers ----------------
__device__ __forceinline__ uint32_t smem_u32(const void* p) {
    uint32_t a;
    asm("{ .reg .u64 t; cvta.to.shared.u64 t, %1; cvt.u32.u64 %0, t; }" : "=r"(a) : "l"(p));
    return a;
}
__device__ __forceinline__ void mma_f16(float& c0, float& c1, float& c2, float& c3,
                                        uint32_t a0, uint32_t a1, uint32_t a2, uint32_t a3,
                                        uint32_t b0, uint32_t b1) {
    asm volatile("mma.sync.aligned.m16n8k16.row.col.f32.f16.f16.f32 "
                 "{%0,%1,%2,%3}, {%4,%5,%6,%7}, {%8,%9}, {%0,%1,%2,%3};"
                 : "+f"(c0), "+f"(c1), "+f"(c2), "+f"(c3)
                 : "r"(a0), "r"(a1), "r"(a2), "r"(a3), "r"(b0), "r"(b1));
}
__device__ __forceinline__ void ldsm_x4(uint32_t& r0, uint32_t& r1, uint32_t& r2, uint32_t& r3,
                                        uint32_t addr) {
    asm volatile("ldmatrix.sync.aligned.m8n8.x4.shared.b16 {%0,%1,%2,%3}, [%4];"
                 : "=r"(r0), "=r"(r1), "=r"(r2), "=r"(r3) : "r"(addr));
}
__device__ __forceinline__ void ldsm_x4_t(uint32_t& r0, uint32_t& r1, uint32_t& r2, uint32_t& r3,
                                          uint32_t addr) {
    asm volatile("ldmatrix.sync.aligned.m8n8.x4.trans.shared.b16 {%0,%1,%2,%3}, [%4];"
                 : "=r"(r0), "=r"(r1), "=r"(r2), "=r"(r3) : "r"(addr));
}
__device__ __forceinline__ void cp16(uint32_t dst, const void* src, int sz) {
    asm volatile("cp.async.cg.shared.global [%0], [%1], 16, %2;"
                 :: "r"(dst), "l"(src), "r"(sz) : "memory");
}
#define CP_COMMIT() asm volatile("cp.async.commit_group;" ::: "memory")
#define CP_WAIT1()  asm volatile("cp.async.wait_group 1;" ::: "memory")
#define CP_WAIT0()  asm volatile("cp.async.wait_group 0;" ::: "memory")

// ---------------- fused weight convert (5 tensors) ----------------
__global__ void wconv5_kernel(const float* a0, __half* b0, int n0,
                              const float* a1, __half* b1, int n1,
                              const float* a2, __half* b2, int n2,
                              const float* a3, __half* b3, int n3,
                              const float* a4, __half* b4, int n4) {
    int stride = gridDim.x * blockDim.x;
    int tot = n0 + n1 + n2 + n3 + n4;
    for (int i = blockIdx.x*blockDim.x + threadIdx.x; i < tot; i += stride) {
        int j = i;
        const float* s; __half* d;
        if (j < n0) { s = a0; d = b0; }
        else { j -= n0;
            if (j < n1) { s = a1; d = b1; }
            else { j -= n1;
                if (j < n2) { s = a2; d = b2; }
                else { j -= n2;
                    if (j < n3) { s = a3; d = b3; }
                    else { j -= n3; s = a4; d = b4; }
                }
            }
        }
        d[j] = __float2half_rn(s[j]);
    }
}

// ---------------- sort ----------------
__global__ void sort_kernel(const float* __restrict__ attn) {
    __shared__ float sv[256];
    __shared__ int   si[256];
    int b = blockIdx.x, t = threadIdx.x;
    sv[t] = (t < NTOK) ? attn[b*NTOK + t] : -INFINITY;
    si[t] = t;
    __syncthreads();
    for (int k = 2; k <= 256; k <<= 1) {
        for (int j = k >> 1; j > 0; j >>= 1) {
            int ix = t ^ j;
            if (ix > t) {
                float v1 = sv[t], v2 = sv[ix];
                int   i1 = si[t], i2 = si[ix];
                bool before = (v1 > v2) || (v1 == v2 && i1 < i2);
                bool doswap = ((t & k) == 0) ? (!before) : before;
                if (doswap) { sv[t]=v2; sv[ix]=v1; si[t]=i2; si[ix]=i1; }
            }
            __syncthreads();
        }
    }
    if (t < NTOK) g_ord[b*NTOK + t] = si[t];
}

// ---------------- gather ----------------
__global__ void gather_kernel(const float* __restrict__ xin) {
    int blk = blockIdx.x;
    int b = blk / 197, r = blk % 197;
    int t = threadIdx.x;
    if (r == 0) {
        const float* srow = xin + (size_t)b*197*C_;
        float* drow = g_x + (size_t)b*N_*C_;
        drow[t] = srow[t]; drow[t+256] = srow[t+256]; drow[t+512] = srow[t+512];
    } else if (r <= SPLN) {
        int i = r - 1;
        int ord = g_ord[b*NTOK + i];
        const float* srow = xin + ((size_t)b*197 + 1 + ord)*C_;
        __half* drow = g_tok + ((size_t)b*SPLN + i)*C_;
        drow[t]     = __float2half_rn(srow[t]);
        drow[t+256] = __float2half_rn(srow[t+256]);
        drow[t+512] = __float2half_rn(srow[t+512]);
    } else {
        int i = r - 1 - SPLN;
        int ord = g_ord[b*NTOK + SPLN + i];
        const float* srow = xin + ((size_t)b*197 + 1 + ord)*C_;
        float* drow = g_x + ((size_t)b*N_ + 1 + SPLN*4 + i)*C_;
        drow[t] = srow[t]; drow[t+256] = srow[t+256]; drow[t+512] = srow[t+512];
    }
}

__global__ void init_kernel() {
    int i = blockIdx.x*blockDim.x + threadIdx.x;
    if (i < B_*(N_-1)) { g_glb[i] = 0.f; g_cls[i] = 0.f; }
}

// ---------------- persistent fp16 GEMM: 128x128 tiles, BK=64, 3-stage cp.async ----------------
// modes: 0 bias->f32 | 1 bias+gelu->HALF | 2 bias+residual->f32 | 3 bias+split-remap->f32 | 4 bias->HALF
#define A_ST 72
#define W_ST 136
#define A_BY (128*A_ST*2)
#define W_BY (64*W_ST*2)
#define BUF_BY (A_BY + W_BY)
#define NSTAGE 3
#define GEMM_SMEM (NSTAGE*BUF_BY)

__global__ __launch_bounds__(256, 2)
void gemm_h(const __half* __restrict__ A, const __half* __restrict__ W,
            const float* __restrict__ bias, const float* __restrict__ resid,
            void* __restrict__ out, int M, int N, int K, int mode) {
    extern __shared__ char smc[];
    int tid  = threadIdx.x;
    int warp = tid >> 5, lane = tid & 31;
    int g    = lane >> 2, tig = lane & 3;
    int wm0  = (warp >> 2) * 64;
    int wn0  = (warp & 3) * 32;

    uint32_t sbase = smem_u32(smc);

    int nt  = K >> 6;
    int ntx = N >> 7;
    int nty = (M + 127) >> 7;
    int ntot = ntx * nty;

    int a_row = lane & 15;
    int a_col = (lane >> 4) << 3;
    int b_krw = (lane & 7) + (((lane >> 4) & 1) << 3);
    int b_ncl = ((lane >> 3) & 1) << 3;

#define ISSUE_TILE(kc_, buf_) do {                                              \
        uint32_t ab = sbase + (uint32_t)(buf_) * BUF_BY;                        \
        uint32_t wb = ab + A_BY;                                               \
        {                                                                       \
            int row = tid >> 1, c = tid & 1;                                    \
            int gr = m0 + row;                                                  \
            int ok = (gr < M);                                                  \
            const __half* src = A + (size_t)(ok ? gr : 0)*K + (kc_)*64 + c*32;  \
            uint32_t d = ab + (uint32_t)row*(A_ST*2) + (uint32_t)c*64;          \
            cp16(d,      src,      ok ? 16 : 0);                                \
            cp16(d + 16, src + 8,  ok ? 16 : 0);                                \
            cp16(d + 32, src + 16, ok ? 16 : 0);                                \
            cp16(d + 48, src + 24, ok ? 16 : 0);                                \
        }                                                                       \
        {                                                                       \
            int kr = tid >> 3, seg = tid & 7;                                   \
            _Pragma("unroll")                                                   \
            for (int rr = 0; rr < 2; rr++) {                                    \
                int r = kr + rr*32;                                             \
                const __half* src = W + (size_t)((kc_)*64 + r)*N + n0 + seg*16; \
                uint32_t d = wb + (uint32_t)r*(W_ST*2) + (uint32_t)seg*32;      \
                cp16(d,      src,     16);                                      \
                cp16(d + 16, src + 8, 16);                                      \
            }                                                                   \
        }                                                                       \
        CP_COMMIT();                                                            \
    } while (0)

    for (int t = blockIdx.x; t < ntot; t += gridDim.x) {
        int m0 = (t / ntx) * 128;
        int n0 = (t % ntx) * 128;

        float acc[4][4][4];
#pragma unroll
        for (int i = 0; i < 4; i++)
#pragma unroll
            for (int j = 0; j < 4; j++)
#pragma unroll
                for (int c = 0; c < 4; c++) acc[i][j][c] = 0.f;

        ISSUE_TILE(0, 0);
        ISSUE_TILE(1, 1);

        for (int kc = 0; kc < nt; kc++) {
            int buf = kc % NSTAGE;
            if (kc == nt - 1) { CP_WAIT0(); } else { CP_WAIT1(); }
            __syncthreads();
            if (kc + 2 < nt) ISSUE_TILE(kc + 2, (kc + 2) % NSTAGE);

            uint32_t ab = sbase + (uint32_t)buf * BUF_BY;
            uint32_t wb = ab + A_BY;
#pragma unroll
            for (int ks = 0; ks < 4; ks++) {
                int k0 = ks * 16;
                uint32_t a[4][4], b[4][2];
#pragma unroll
                for (int mi = 0; mi < 4; mi++) {
                    uint32_t addr = ab + (uint32_t)((wm0 + mi*16 + a_row)*A_ST + k0 + a_col)*2;
                    ldsm_x4(a[mi][0], a[mi][1], a[mi][2], a[mi][3], addr);
                }
#pragma unroll
                for (int np = 0; np < 2; np++) {
                    uint32_t addr = wb + (uint32_t)((k0 + b_krw)*W_ST + wn0 + np*16 + b_ncl)*2;
                    uint32_t r0, r1, r2, r3;
                    ldsm_x4_t(r0, r1, r2, r3, addr);
                    b[np*2][0]   = r0; b[np*2][1]   = r2;
                    b[np*2+1][0] = r1; b[np*2+1][1] = r3;
                }
#pragma unroll
                for (int mi = 0; mi < 4; mi++)
#pragma unroll
                    for (int ni = 0; ni < 4; ni++)
                        mma_f16(acc[mi][ni][0], acc[mi][ni][1], acc[mi][ni][2], acc[mi][ni][3],
                                a[mi][0], a[mi][1], a[mi][2], a[mi][3],
                                b[ni][0], b[ni][1]);
            }
        }

        // epilogue
#pragma unroll
        for (int mi = 0; mi < 4; mi++) {
#pragma unroll
            for (int half_ = 0; half_ < 2; half_++) {
                int row = m0 + wm0 + mi*16 + g + half_*8;
                if (row >= M) continue;
#pragma unroll
                for (int ni = 0; ni < 4; ni++) {
                    int col = n0 + wn0 + ni*8 + tig*2;
                    float v0 = acc[mi][ni][half_*2]     + bias[col];
                    float v1 = acc[mi][ni][half_*2 + 1] + bias[col+1];
                    if (mode == 1) {
                        v0 = 0.5f*v0*(1.0f + erff(v0*0.70710678118654752f));
                        v1 = 0.5f*v1*(1.0f + erff(v1*0.70710678118654752f));
                        *(__half2*)((__half*)out + (size_t)row*N + col) =
                            __floats2half2_rn(v0, v1);
                    } else if (mode == 4) {
                        *(__half2*)((__half*)out + (size_t)row*N + col) =
                            __floats2half2_rn(v0, v1);
                    } else if (mode == 2) {
                        const float* rrow = resid + (size_t)row*N;
                        v0 += rrow[col];
                        v1 += rrow[col+1];
                        *(float2*)((float*)out + (size_t)row*N + col) = make_float2(v0, v1);
                    } else if (mode == 3) {
                        int bb = row / SPLN, s = row % SPLN;
                        float* orow = (float*)out + ((size_t)bb*N_ + 1 + (size_t)s*4)*C_;
                        *(float2*)(orow + col) = make_float2(v0, v1);
                    } else {
                        *(float2*)((float*)out + (size_t)row*N + col) = make_float2(v0, v1);
                    }
                }
            }
        }
    }
#undef ISSUE_TILE
}

// ---------------- layernorm: warp per row ----------------
__global__ __launch_bounds__(256)
void ln_kernel(const float* __restrict__ in, __half* __restrict__ out,
               const float* __restrict__ gamma, const float* __restrict__ beta) {
    int warp = threadIdx.x >> 5, lane = threadIdx.x & 31;
    int row = blockIdx.x * 8 + warp;
    if (row >= M_ROWS) return;
    const float4* xr = (const float4*)(in + (size_t)row * C_);
    float4 v[6];
    float s = 0.f;
#pragma unroll
    for (int i = 0; i < 6; i++) {
        v[i] = xr[lane + i*32];
        s += v[i].x + v[i].y + v[i].z + v[i].w;
    }
#pragma unroll
    for (int o = 16; o; o >>= 1) s += __shfl_xor_sync(~0u, s, o);
    float mean = s * (1.0f / C_);
    float s2 = 0.f;
#pragma unroll
    for (int i = 0; i < 6; i++) {
        float a = v[i].x - mean, b = v[i].y - mean, c = v[i].z - mean, d = v[i].w - mean;
        s2 += a*a + b*b + c*c + d*d;
    }
#pragma unroll
    for (int o = 16; o; o >>= 1) s2 += __shfl_xor_sync(~0u, s2, o);
    float inv = rsqrtf(s2 * (1.0f / C_) + 1e-6f);
    __half2* orow = (__half2*)(out + (size_t)row * C_);
#pragma unroll
    for (int i = 0; i < 6; i++) {
        int c0 = (lane + i*32) * 4;
        float4 gm = *(const float4*)(gamma + c0);
        float4 bt = *(const float4*)(beta  + c0);
        orow[c0/2]     = __floats2half2_rn((v[i].x - mean)*inv*gm.x + bt.x,
                                           (v[i].y - mean)*inv*gm.y + bt.y);
        orow[c0/2 + 1] = __floats2half2_rn((v[i].z - mean)*inv*gm.z + bt.z,
                                           (v[i].w - mean)*inv*gm.w + bt.w);
    }
}

// ---------------- fp16 flash attention, 128 q-rows per CTA; row-0 scores exported ----------------
#define FA_SMEM 73728
__global__ __launch_bounds__(256)
void flash_attn(const __half* __restrict__ qkv, __half* __restrict__ obuf,
                float* __restrict__ srow_out) {
    extern __shared__ __half sh[];
    __half* Qs = sh;
    __half* Ps = sh + 27648;

    int bh = blockIdx.y;
    int b = bh / H_, h = bh % H_;
    int q0 = blockIdx.x * 128;
    int tid = threadIdx.x, warp = tid >> 5, lane = tid & 31;
    int g = lane >> 2, tig = lane & 3;
    const __half* base = qkv + (size_t)b * N_ * (3*C_) + h * D_;
    uint32_t sb = smem_u32(sh);

    {
        const uint4 z = make_uint4(0,0,0,0);
        for (int idx = tid; idx < 128*8; idx += 256) {
            int r = idx >> 3, c8 = idx & 7;
            int qr = q0 + r;
            uint4 v = z;
            if (qr < N_) v = *(const uint4*)(base + (size_t)qr*(3*C_) + c8*8);
            *(uint4*)(Qs + r*72 + c8*8) = v;
        }
    }

#define FA_ISSUE(kt_, buf_) do {                                              \
        uint32_t kb8 = sb + (uint32_t)(9216 + (buf_)*4608)*2u;                \
        uint32_t vb8 = sb + (uint32_t)(18432 + (buf_)*4608)*2u;               \
        _Pragma("unroll")                                                     \
        for (int it = 0; it < 2; it++) {                                      \
            int chunk = tid + it*256;                                         \
            int r = chunk >> 3, c8 = chunk & 7;                               \
            int kr = (kt_)*64 + r;                                            \
            int ok = (kr < N_);                                               \
            const __half* ksrc = base + (size_t)(ok ? kr : 0)*(3*C_) + C_   + c8*8; \
            const __half* vsrc = base + (size_t)(ok ? kr : 0)*(3*C_) + 2*C_ + c8*8; \
            cp16(kb8 + (uint32_t)(r*72 + c8*8)*2u, ksrc, ok ? 16 : 0);        \
            cp16(vb8 + (uint32_t)(r*72 + c8*8)*2u, vsrc, ok ? 16 : 0);        \
        }                                                                     \
        CP_COMMIT();                                                          \
    } while (0)

    FA_ISSUE(0, 0);
    FA_ISSUE(1, 1);

    float o[8][4];
#pragma unroll
    for (int i = 0; i < 8; i++) { o[i][0]=0.f; o[i][1]=0.f; o[i][2]=0.f; o[i][3]=0.f; }
    float mr0 = -INFINITY, mr1 = -INFINITY, l0 = 0.f, l1 = 0.f;

    __half* Pw = Ps + warp*16*72;

    int a_row = lane & 15;
    int a_col = (lane >> 4) << 3;
    int kb_nrow = (lane & 7) + ((lane >> 4) << 3);
    int kb_koff = ((lane >> 3) & 1) << 3;
    int vb_krw  = (lane & 7) + (((lane >> 4) & 1) << 3);
    int vb_ncl  = ((lane >> 3) & 1) << 3;

    uint32_t Qw_s = sb + (uint32_t)(warp*16*72)*2u;
    uint32_t Pw_s = sb + (uint32_t)(27648 + warp*16*72)*2u;

    bool cls_owner = (q0 == 0) && (warp == 0) && ((lane >> 2) == 0);

    for (int kt = 0; kt < 8; kt++) {
        int buf = kt & 1;
        if (kt == 7) { CP_WAIT0(); } else { CP_WAIT1(); }
        __syncthreads();
        uint32_t Kt_s = sb + (uint32_t)(9216  + buf*4608)*2u;
        uint32_t Vt_s = sb + (uint32_t)(18432 + buf*4608)*2u;

        float s[8][4];
#pragma unroll
        for (int i = 0; i < 8; i++) { s[i][0]=0.f; s[i][1]=0.f; s[i][2]=0.f; s[i][3]=0.f; }
#pragma unroll
        for (int ks = 0; ks < 4; ks++) {
            int k0 = ks * 16;
            uint32_t a0, a1, a2, a3;
            ldsm_x4(a0, a1, a2, a3, Qw_s + (uint32_t)(a_row*72 + k0 + a_col)*2u);
#pragma unroll
            for (int np = 0; np < 4; np++) {
                int nb = np * 16;
                uint32_t r0, r1, r2, r3;
                ldsm_x4(r0, r1, r2, r3, Kt_s + (uint32_t)((nb + kb_nrow)*72 + k0 + kb_koff)*2u);
                mma_f16(s[np*2][0],   s[np*2][1],   s[np*2][2],   s[np*2][3],   a0,a1,a2,a3, r0, r1);
                mma_f16(s[np*2+1][0], s[np*2+1][1], s[np*2+1][2], s[np*2+1][3], a0,a1,a2,a3, r2, r3);
            }
        }
        float mc0 = -INFINITY, mc1 = -INFINITY;
#pragma unroll
        for (int ni = 0; ni < 8; ni++) {
            int colb = kt*64 + ni*8 + 2*tig;
#pragma unroll
            for (int cc = 0; cc < 4; cc++) {
                float v = s[ni][cc] * 0.125f;
                if (colb + (cc & 1) >= N_) v = -INFINITY;
                s[ni][cc] = v;
                if (cc < 2) mc0 = fmaxf(mc0, v); else mc1 = fmaxf(mc1, v);
            }
        }
        if (cls_owner) {
            float* sr = srow_out + (size_t)bh*512 + kt*64;
#pragma unroll
            for (int ni = 0; ni < 8; ni++) {
                sr[ni*8 + 2*tig]     = s[ni][0];
                sr[ni*8 + 2*tig + 1] = s[ni][1];
            }
        }
        mc0 = fmaxf(mc0, __shfl_xor_sync(~0u, mc0, 1));
        mc0 = fmaxf(mc0, __shfl_xor_sync(~0u, mc0, 2));
        mc1 = fmaxf(mc1, __shfl_xor_sync(~0u, mc1, 1));
        mc1 = fmaxf(mc1, __shfl_xor_sync(~0u, mc1, 2));
        float mn0 = fmaxf(mr0, mc0), mn1 = fmaxf(mr1, mc1);
        float al0 = expf(mr0 - mn0), al1 = expf(mr1 - mn1);
        mr0 = mn0; mr1 = mn1;
        float ls0 = 0.f, ls1 = 0.f;
#pragma unroll
        for (int ni = 0; ni < 8; ni++) {
            float p0 = expf(s[ni][0] - mn0);
            float p1 = expf(s[ni][1] - mn0);
            float p2 = expf(s[ni][2] - mn1);
            float p3 = expf(s[ni][3] - mn1);
            s[ni][0]=p0; s[ni][1]=p1; s[ni][2]=p2; s[ni][3]=p3;
            ls0 += p0 + p1; ls1 += p2 + p3;
        }
        ls0 += __shfl_xor_sync(~0u, ls0, 1); ls0 += __shfl_xor_sync(~0u, ls0, 2);
        ls1 += __shfl_xor_sync(~0u, ls1, 1); ls1 += __shfl_xor_sync(~0u, ls1, 2);
        l0 = l0*al0 + ls0; l1 = l1*al1 + ls1;

        __syncwarp();
#pragma unroll
        for (int ni = 0; ni < 8; ni++) {
            *(__half2*)(Pw + g*72     + ni*8 + 2*tig) = __floats2half2_rn(s[ni][0], s[ni][1]);
            *(__half2*)(Pw + (g+8)*72 + ni*8 + 2*tig) = __floats2half2_rn(s[ni][2], s[ni][3]);
        }
#pragma unroll
        for (int ni = 0; ni < 8; ni++) {
            o[ni][0]*=al0; o[ni][1]*=al0; o[ni][2]*=al1; o[ni][3]*=al1;
        }
        __syncwarp();
#pragma unroll
        for (int ks = 0; ks < 4; ks++) {
            int k0 = ks * 16;
            uint32_t a0, a1, a2, a3;
            ldsm_x4(a0, a1, a2, a3, Pw_s + (uint32_t)(a_row*72 + k0 + a_col)*2u);
#pragma unroll
            for (int np = 0; np < 4; np++) {
                int nb = np * 16;
                uint32_t r0, r1, r2, r3;
                ldsm_x4_t(r0, r1, r2, r3, Vt_s + (uint32_t)((k0 + vb_krw)*72 + nb + vb_ncl)*2u);
                mma_f16(o[np*2][0],   o[np*2][1],   o[np*2][2],   o[np*2][3],   a0,a1,a2,a3, r0, r2);
                mma_f16(o[np*2+1][0], o[np*2+1][1], o[np*2+1][2], o[np*2+1][3], a0,a1,a2,a3, r1, r3);
            }
        }
        __syncthreads();
        if (kt + 2 < 8) FA_ISSUE(kt + 2, buf);
    }
#undef FA_ISSUE

    int r0 = q0 + warp*16 + g, r1 = r0 + 8;
    float inv0 = 1.f / l0, inv1 = 1.f / l1;
#pragma unroll
    for (int ni = 0; ni < 8; ni++) {
        int col = h*D_ + ni*8 + 2*tig;
        if (r0 < N_)
            *(__half2*)(obuf + ((size_t)b*N_ + r0)*C_ + col) =
                __floats2half2_rn(o[ni][0]*inv0, o[ni][1]*inv0);
        if (r1 < N_)
            *(__half2*)(obuf + ((size_t)b*N_ + r1)*C_ + col) =
                __floats2half2_rn(o[ni][2]*inv1, o[ni][3]*inv1);
    }
}

// ---------------- cls softmax over exported row-0 scores ----------------
__global__ __launch_bounds__(512)
void cls2_kernel(const float* __restrict__ srow, float* __restrict__ cls_acc) {
    __shared__ float red[16];
    int bh = blockIdx.x;
    int b = bh / H_;
    int tid = threadIdx.x, lane = tid & 31, warp = tid >> 5;
    float v = (tid < N_) ? srow[(size_t)bh*512 + tid] : -INFINITY;
    float m = v;
#pragma unroll
    for (int o = 16; o; o >>= 1) m = fmaxf(m, __shfl_xor_sync(~0u, m, o));
    if (lane == 0) red[warp] = m;
    __syncthreads();
    float M = red[0];
#pragma unroll
    for (int i = 1; i < 16; i++) M = fmaxf(M, red[i]);
    __syncthreads();
    float e = (tid < N_) ? expf(v - M) : 0.f;
    float t = e;
#pragma unroll
    for (int o = 16; o; o >>= 1) t += __shfl_xor_sync(~0u, t, o);
    if (lane == 0) red[warp] = t;
    __syncthreads();
    float L = 0.f;
#pragma unroll
    for (int i = 0; i < 16; i++) L += red[i];
    if (tid >= 1 && tid < N_)
        atomicAdd(&cls_acc[b*(N_-1) + tid - 1], e / (L * (float)H_));
}

// ---------------- glb EMA ----------------
__global__ void glb_kernel() {
    int i = blockIdx.x*blockDim.x + threadIdx.x;
    if (i < B_*(N_-1)) {
        g_glb[i] = 0.5f * g_glb[i] + 0.5f * g_cls[i];
        g_cls[i] = 0.f;
    }
}

// ---------------- glb output copy ----------------
__global__ void copy_glb_kernel(float* __restrict__ out) {
    int i = blockIdx.x*blockDim.x + threadIdx.x;
    if (i < B_*(N_-1)) out[(size_t)B_*N_*C_ + i] = g_glb[i];
}

// ---------------- launch ----------------
extern "C" void kernel_launch(void* const* d_in, const int* in_sizes, int n_in,
                              void* d_out, int out_size) {
    const float* x       = (const float*)d_in[0];
    const float* gattn   = (const float*)d_in[1];
    const float* split_w = (const float*)d_in[2];
    const float* split_b = (const float*)d_in[3];
    const float* ln1_g   = (const float*)d_in[4];
    const float* ln1_b   = (const float*)d_in[5];
    const float* qkv_w   = (const float*)d_in[6];
    const float* qkv_b   = (const float*)d_in[7];
    const float* proj_w  = (const float*)d_in[8];
    const float* proj_b  = (const float*)d_in[9];
    const float* ln2_g   = (const float*)d_in[10];
    const float* ln2_b   = (const float*)d_in[11];
    const float* fc1_w   = (const float*)d_in[12];
    const float* fc1_b   = (const float*)d_in[13];
    const float* fc2_w   = (const float*)d_in[14];
    const float* fc2_b   = (const float*)d_in[15];

    float *px, *pcls, *psrow;
    __half *ph, *pqkv, *po, *pmlp, *ptok;
    __half *pwsplit, *pwqkv, *pwproj, *pwfc1, *pwfc2;
    cudaGetSymbolAddress((void**)&px,   g_x);
    cudaGetSymbolAddress((void**)&ph,   g_h);
    cudaGetSymbolAddress((void**)&pqkv, g_qkv);
    cudaGetSymbolAddress((void**)&po,   g_o);
    cudaGetSymbolAddress((void**)&pmlp, g_mlp);
    cudaGetSymbolAddress((void**)&ptok, g_tok);
    cudaGetSymbolAddress((void**)&pcls, g_cls);
    cudaGetSymbolAddress((void**)&psrow, g_srow);
    cudaGetSymbolAddress((void**)&pwsplit, g_wsplit);
    cudaGetSymbolAddress((void**)&pwqkv,   g_wqkv);
    cudaGetSymbolAddress((void**)&pwproj,  g_wproj);
    cudaGetSymbolAddress((void**)&pwfc1,   g_wfc1);
    cudaGetSymbolAddress((void**)&pwfc2,   g_wfc2);

    cudaFuncSetAttribute(gemm_h,     cudaFuncAttributeMaxDynamicSharedMemorySize, GEMM_SMEM);
    cudaFuncSetAttribute(flash_attn, cudaFuncAttributeMaxDynamicSharedMemorySize, FA_SMEM);

    wconv5_kernel<<<2048, 256>>>(split_w, pwsplit, SW_SZ,
                                 qkv_w,   pwqkv,   L_*QW_SZ,
                                 proj_w,  pwproj,  L_*PW_SZ,
                                 fc1_w,   pwfc1,   L_*F1_SZ,
                                 fc2_w,   pwfc2,   L_*F2_SZ);
    sort_kernel<<<B_, 256>>>(gattn);
    gather_kernel<<<B_*197, 256>>>(x);
    init_kernel<<<(B_*(N_-1) + 255)/256, 256>>>();

    {   // split GEMM  M=1568, N=3072, K=768
        gemm_h<<<PERSIST_CTAS, 256, GEMM_SMEM>>>(ptok, pwsplit, split_b, nullptr, px,
                                                 B_*SPLN, 4*C_, C_, 3);
    }

    for (int l = 0; l < L_; l++) {
        const float* l1g = ln1_g + l*C_;
        const float* l1b = ln1_b + l*C_;
        const __half* qw = pwqkv + (size_t)l*QW_SZ;
        const float* qb  = qkv_b + l*3*C_;
        const __half* pw = pwproj + (size_t)l*PW_SZ;
        const float* pb  = proj_b + l*C_;
        const float* l2g = ln2_g + l*C_;
        const float* l2b = ln2_b + l*C_;
        const __half* w1 = pwfc1 + (size_t)l*F1_SZ;
        const float* b1  = fc1_b + l*HM_;
        const __half* w2 = pwfc2 + (size_t)l*F2_SZ;
        const float* b2  = fc2_b + l*C_;

        ln_kernel<<<(M_ROWS + 7)/8, 256>>>(px, ph, l1g, l1b);

        gemm_h<<<PERSIST_CTAS, 256, GEMM_SMEM>>>(ph, qw, qb, nullptr, pqkv,
                                                 M_ROWS, 3*C_, C_, 4);

        { dim3 grid(4, B_*H_);
          flash_attn<<<grid, 256, FA_SMEM>>>(pqkv, po, psrow); }

        cls2_kernel<<<B_*H_, 512>>>(psrow, pcls);

        glb_kernel<<<(B_*(N_-1) + 255)/256, 256>>>();

        gemm_h<<<PERSIST_CTAS, 256, GEMM_SMEM>>>(po, pw, pb, px, px,
                                                 M_ROWS, C_, C_, 2);

        ln_kernel<<<(M_ROWS + 7)/8, 256>>>(px, ph, l2g, l2b);

        gemm_h<<<PERSIST_CTAS, 256, GEMM_SMEM>>>(ph, w1, b1, nullptr, pmlp,
                                                 M_ROWS, HM_, C_, 1);

        {   // fc2: final layer writes x directly into d_out
            float* xdst = (l == L_ - 1) ? (float*)d_out : px;
            gemm_h<<<PERSIST_CTAS, 256, GEMM_SMEM>>>(pmlp, w2, b2, px, xdst,
                                                     M_ROWS, C_, HM_, 2);
        }
    }

    copy_glb_kernel<<<(B_*(N_-1) + 255)/256, 256>>>((float*)d_out);
}

// round 13
// speedup vs baseline: 1.0032x; 1.0032x over previous
#include <cuda_runtime.h>
#include <cuda_fp16.h>
#include <math.h>
#include <stdint.h>

// ---------------- problem constants ----------------
#define B_    16
#define NTOK  196
#define SPLN  98
#define N_    491          // 1 + 98*4 + 98
#define C_    768
#define HM_   3072
#define H_    12
#define D_    64
#define L_    4
#define M_ROWS (B_*N_)     // 7856

// weight sizes
#define SW_SZ   (C_*4*C_)
#define QW_SZ   (C_*3*C_)
#define PW_SZ   (C_*C_)
#define F1_SZ   (C_*HM_)
#define F2_SZ   (HM_*C_)

// ---------------- device scratch ----------------
__device__ float  g_x   [B_*N_*C_];
__device__ __half g_h   [B_*N_*C_];
__device__ __half g_qkv [B_*N_*3*C_];
__device__ __half g_o   [B_*N_*C_];
__device__ __half g_mlp [B_*N_*HM_];
__device__ __half g_tok [B_*SPLN*C_];
__device__ int    g_ord [B_*NTOK];
__device__ float  g_glb [B_*(N_-1)];
__device__ float  g_cls [B_*(N_-1)];
__device__ float  g_srow[B_*H_*512];
// fp16 weights
__device__ __half g_wsplit[SW_SZ];
__device__ __half g_wqkv  [L_*QW_SZ];
__device__ __half g_wproj [L_*PW_SZ];
__device__ __half g_wfc1  [L_*F1_SZ];
__device__ __half g_wfc2  [L_*F2_SZ];

// ---------------- helpers ----------------
__device__ __forceinline__ uint32_t smem_u32(const void* p) {
    uint32_t a;
    asm("{ .reg .u64 t; cvta.to.shared.u64 t, %1; cvt.u32.u64 %0, t; }" : "=r"(a) : "l"(p));
    return a;
}
__device__ __forceinline__ void mma_f16(float& c0, float& c1, float& c2, float& c3,
                                        uint32_t a0, uint32_t a1, uint32_t a2, uint32_t a3,
                                        uint32_t b0, uint32_t b1) {
    asm volatile("mma.sync.aligned.m16n8k16.row.col.f32.f16.f16.f32 "
                 "{%0,%1,%2,%3}, {%4,%5,%6,%7}, {%8,%9}, {%0,%1,%2,%3};"
                 : "+f"(c0), "+f"(c1), "+f"(c2), "+f"(c3)
                 : "r"(a0), "r"(a1), "r"(a2), "r"(a3), "r"(b0), "r"(b1));
}
__device__ __forceinline__ void ldsm_x4(uint32_t& r0, uint32_t& r1, uint32_t& r2, uint32_t& r3,
                                        uint32_t addr) {
    asm volatile("ldmatrix.sync.aligned.m8n8.x4.shared.b16 {%0,%1,%2,%3}, [%4];"
                 : "=r"(r0), "=r"(r1), "=r"(r2), "=r"(r3) : "r"(addr));
}
__device__ __forceinline__ void ldsm_x4_t(uint32_t& r0, uint32_t& r1, uint32_t& r2, uint32_t& r3,
                                          uint32_t addr) {
    asm volatile("ldmatrix.sync.aligned.m8n8.x4.trans.shared.b16 {%0,%1,%2,%3}, [%4];"
                 : "=r"(r0), "=r"(r1), "=r"(r2), "=r"(r3) : "r"(addr));
}
__device__ __forceinline__ void cp16(uint32_t dst, const void* src, int sz) {
    asm volatile("cp.async.cg.shared.global [%0], [%1], 16, %2;"
                 :: "r"(dst), "l"(src), "r"(sz) : "memory");
}
#define CP_COMMIT() asm volatile("cp.async.commit_group;" ::: "memory")
#define CP_WAIT1()  asm volatile("cp.async.wait_group 1;" ::: "memory")
#define CP_WAIT0()  asm volatile("cp.async.wait_group 0;" ::: "memory")

// ---------------- fused weight convert (5 tensors) ----------------
__global__ void wconv5_kernel(const float* a0, __half* b0, int n0,
                              const float* a1, __half* b1, int n1,
                              const float* a2, __half* b2, int n2,
                              const float* a3, __half* b3, int n3,
                              const float* a4, __half* b4, int n4) {
    int stride = gridDim.x * blockDim.x;
    int tot = n0 + n1 + n2 + n3 + n4;
    for (int i = blockIdx.x*blockDim.x + threadIdx.x; i < tot; i += stride) {
        int j = i;
        const float* s; __half* d;
        if (j < n0) { s = a0; d = b0; }
        else { j -= n0;
            if (j < n1) { s = a1; d = b1; }
            else { j -= n1;
                if (j < n2) { s = a2; d = b2; }
                else { j -= n2;
                    if (j < n3) { s = a3; d = b3; }
                    else { j -= n3; s = a4; d = b4; }
                }
            }
        }
        d[j] = __float2half_rn(s[j]);
    }
}

// ---------------- sort ----------------
__global__ void sort_kernel(const float* __restrict__ attn) {
    __shared__ float sv[256];
    __shared__ int   si[256];
    int b = blockIdx.x, t = threadIdx.x;
    sv[t] = (t < NTOK) ? attn[b*NTOK + t] : -INFINITY;
    si[t] = t;
    __syncthreads();
    for (int k = 2; k <= 256; k <<= 1) {
        for (int j = k >> 1; j > 0; j >>= 1) {
            int ix = t ^ j;
            if (ix > t) {
                float v1 = sv[t], v2 = sv[ix];
                int   i1 = si[t], i2 = si[ix];
                bool before = (v1 > v2) || (v1 == v2 && i1 < i2);
                bool doswap = ((t & k) == 0) ? (!before) : before;
                if (doswap) { sv[t]=v2; sv[ix]=v1; si[t]=i2; si[ix]=i1; }
            }
            __syncthreads();
        }
    }
    if (t < NTOK) g_ord[b*NTOK + t] = si[t];
}

// ---------------- gather ----------------
__global__ void gather_kernel(const float* __restrict__ xin) {
    int blk = blockIdx.x;
    int b = blk / 197, r = blk % 197;
    int t = threadIdx.x;
    if (r == 0) {
        const float* srow = xin + (size_t)b*197*C_;
        float* drow = g_x + (size_t)b*N_*C_;
        drow[t] = srow[t]; drow[t+256] = srow[t+256]; drow[t+512] = srow[t+512];
    } else if (r <= SPLN) {
        int i = r - 1;
        int ord = g_ord[b*NTOK + i];
        const float* srow = xin + ((size_t)b*197 + 1 + ord)*C_;
        __half* drow = g_tok + ((size_t)b*SPLN + i)*C_;
        drow[t]     = __float2half_rn(srow[t]);
        drow[t+256] = __float2half_rn(srow[t+256]);
        drow[t+512] = __float2half_rn(srow[t+512]);
    } else {
        int i = r - 1 - SPLN;
        int ord = g_ord[b*NTOK + SPLN + i];
        const float* srow = xin + ((size_t)b*197 + 1 + ord)*C_;
        float* drow = g_x + ((size_t)b*N_ + 1 + SPLN*4 + i)*C_;
        drow[t] = srow[t]; drow[t+256] = srow[t+256]; drow[t+512] = srow[t+512];
    }
}

__global__ void init_kernel() {
    int i = blockIdx.x*blockDim.x + threadIdx.x;
    if (i < B_*(N_-1)) { g_glb[i] = 0.f; g_cls[i] = 0.f; }
}

// =============== fp16 GEMM 128x128 tile, BK=64, warp 64x32, 3-stage cp.async ===============
// modes: 0 bias->f32 | 1 bias+gelu->HALF | 2 bias+residual->f32 | 3 bias+split-remap->f32 | 4 bias->HALF
#define A_ST 72
#define W_ST 136
#define A_BY (128*A_ST*2)
#define W_BY (64*W_ST*2)
#define BUF_BY (A_BY + W_BY)
#define NSTAGE 3
#define GEMM_SMEM (NSTAGE*BUF_BY)

__global__ __launch_bounds__(256, 2)
void gemm_h(const __half* __restrict__ A, const __half* __restrict__ W,
            const float* __restrict__ bias, const float* __restrict__ resid,
            void* __restrict__ out, int M, int N, int K, int mode) {
    extern __shared__ char smc[];
    int tid  = threadIdx.x;
    int m0   = blockIdx.y * 128, n0 = blockIdx.x * 128;
    int warp = tid >> 5, lane = tid & 31;
    int g    = lane >> 2, tig = lane & 3;
    int wm0  = (warp >> 2) * 64;
    int wn0  = (warp & 3) * 32;

    uint32_t sbase = smem_u32(smc);

    float acc[4][4][4];
#pragma unroll
    for (int i = 0; i < 4; i++)
#pragma unroll
        for (int j = 0; j < 4; j++)
#pragma unroll
            for (int c = 0; c < 4; c++) acc[i][j][c] = 0.f;

    int nt = K >> 6;

#define ISSUE_TILE(kc_, buf_) do {                                              \
        uint32_t ab = sbase + (uint32_t)(buf_) * BUF_BY;                        \
        uint32_t wb = ab + A_BY;                                               \
        {                                                                       \
            int row = tid >> 1, c = tid & 1;                                    \
            int gr = m0 + row;                                                  \
            int ok = (gr < M);                                                  \
            const __half* src = A + (size_t)(ok ? gr : 0)*K + (kc_)*64 + c*32;  \
            uint32_t d = ab + (uint32_t)row*(A_ST*2) + (uint32_t)c*64;          \
            cp16(d,      src,      ok ? 16 : 0);                                \
            cp16(d + 16, src + 8,  ok ? 16 : 0);                                \
            cp16(d + 32, src + 16, ok ? 16 : 0);                                \
            cp16(d + 48, src + 24, ok ? 16 : 0);                                \
        }                                                                       \
        {                                                                       \
            int kr = tid >> 3, seg = tid & 7;                                   \
            _Pragma("unroll")                                                   \
            for (int rr = 0; rr < 2; rr++) {                                    \
                int r = kr + rr*32;                                             \
                const __half* src = W + (size_t)((kc_)*64 + r)*N + n0 + seg*16; \
                uint32_t d = wb + (uint32_t)r*(W_ST*2) + (uint32_t)seg*32;      \
                cp16(d,      src,     16);                                      \
                cp16(d + 16, src + 8, 16);                                      \
            }                                                                   \
        }                                                                       \
        CP_COMMIT();                                                            \
    } while (0)

    ISSUE_TILE(0, 0);
    ISSUE_TILE(1, 1);

    int a_row = lane & 15;
    int a_col = (lane >> 4) << 3;
    int b_krw = (lane & 7) + (((lane >> 4) & 1) << 3);
    int b_ncl = ((lane >> 3) & 1) << 3;

    for (int kc = 0; kc < nt; kc++) {
        int buf = kc % NSTAGE;
        if (kc == nt - 1) { CP_WAIT0(); } else { CP_WAIT1(); }
        __syncthreads();
        if (kc + 2 < nt) ISSUE_TILE(kc + 2, (kc + 2) % NSTAGE);

        uint32_t ab = sbase + (uint32_t)buf * BUF_BY;
        uint32_t wb = ab + A_BY;
#pragma unroll
        for (int ks = 0; ks < 4; ks++) {
            int k0 = ks * 16;
            uint32_t a[4][4], b[4][2];
#pragma unroll
            for (int mi = 0; mi < 4; mi++) {
                uint32_t addr = ab + (uint32_t)((wm0 + mi*16 + a_row)*A_ST + k0 + a_col)*2;
                ldsm_x4(a[mi][0], a[mi][1], a[mi][2], a[mi][3], addr);
            }
#pragma unroll
            for (int np = 0; np < 2; np++) {
                uint32_t addr = wb + (uint32_t)((k0 + b_krw)*W_ST + wn0 + np*16 + b_ncl)*2;
                uint32_t r0, r1, r2, r3;
                ldsm_x4_t(r0, r1, r2, r3, addr);
                b[np*2][0]   = r0; b[np*2][1]   = r2;
                b[np*2+1][0] = r1; b[np*2+1][1] = r3;
            }
#pragma unroll
            for (int mi = 0; mi < 4; mi++)
#pragma unroll
                for (int ni = 0; ni < 4; ni++)
                    mma_f16(acc[mi][ni][0], acc[mi][ni][1], acc[mi][ni][2], acc[mi][ni][3],
                            a[mi][0], a[mi][1], a[mi][2], a[mi][3],
                            b[ni][0], b[ni][1]);
        }
    }
#undef ISSUE_TILE

#pragma unroll
    for (int mi = 0; mi < 4; mi++) {
#pragma unroll
        for (int half_ = 0; half_ < 2; half_++) {
            int row = m0 + wm0 + mi*16 + g + half_*8;
            if (row >= M) continue;
#pragma unroll
            for (int ni = 0; ni < 4; ni++) {
                int col = n0 + wn0 + ni*8 + tig*2;
                float v0 = acc[mi][ni][half_*2]     + bias[col];
                float v1 = acc[mi][ni][half_*2 + 1] + bias[col+1];
                if (mode == 1) {
                    v0 = 0.5f*v0*(1.0f + erff(v0*0.70710678118654752f));
                    v1 = 0.5f*v1*(1.0f + erff(v1*0.70710678118654752f));
                    *(__half2*)((__half*)out + (size_t)row*N + col) =
                        __floats2half2_rn(v0, v1);
                } else if (mode == 4) {
                    *(__half2*)((__half*)out + (size_t)row*N + col) =
                        __floats2half2_rn(v0, v1);
                } else if (mode == 2) {
                    const float* rrow = resid + (size_t)row*N;
                    v0 += rrow[col];
                    v1 += rrow[col+1];
                    *(float2*)((float*)out + (size_t)row*N + col) = make_float2(v0, v1);
                } else if (mode == 3) {
                    int bb = row / SPLN, s = row % SPLN;
                    float* orow = (float*)out + ((size_t)bb*N_ + 1 + (size_t)s*4)*C_;
                    *(float2*)(orow + col) = make_float2(v0, v1);
                } else {
                    *(float2*)((float*)out + (size_t)row*N + col) = make_float2(v0, v1);
                }
            }
        }
    }
}

// =============== fp16 GEMM 128x64 tile, BK=64, warp 32x32 (4Mx2N), 3-stage cp.async ===============
#define W64_ST 72
#define W64_BY (64*W64_ST*2)          // 9216
#define BUF64_BY (A_BY + W64_BY)      // 27648
#define GEMM64_SMEM (NSTAGE*BUF64_BY) // 82944

__global__ __launch_bounds__(256, 2)
void gemm_h64(const __half* __restrict__ A, const __half* __restrict__ W,
              const float* __restrict__ bias, const float* __restrict__ resid,
              void* __restrict__ out, int M, int N, int K, int mode) {
    extern __shared__ char smc[];
    int tid  = threadIdx.x;
    int m0   = blockIdx.y * 128, n0 = blockIdx.x * 64;
    int warp = tid >> 5, lane = tid & 31;
    int g    = lane >> 2, tig = lane & 3;
    int wm0  = (warp >> 1) * 32;      // 4 warps in M
    int wn0  = (warp & 1) * 32;       // 2 warps in N

    uint32_t sbase = smem_u32(smc);

    float acc[2][4][4];
#pragma unroll
    for (int i = 0; i < 2; i++)
#pragma unroll
        for (int j = 0; j < 4; j++)
#pragma unroll
            for (int c = 0; c < 4; c++) acc[i][j][c] = 0.f;

    int nt = K >> 6;

#define ISSUE_TILE64(kc_, buf_) do {                                            \
        uint32_t ab = sbase + (uint32_t)(buf_) * BUF64_BY;                      \
        uint32_t wb = ab + A_BY;                                               \
        {                                                                       \
            int row = tid >> 1, c = tid & 1;                                    \
            int gr = m0 + row;                                                  \
            int ok = (gr < M);                                                  \
            const __half* src = A + (size_t)(ok ? gr : 0)*K + (kc_)*64 + c*32;  \
            uint32_t d = ab + (uint32_t)row*(A_ST*2) + (uint32_t)c*64;          \
            cp16(d,      src,      ok ? 16 : 0);                                \
            cp16(d + 16, src + 8,  ok ? 16 : 0);                                \
            cp16(d + 32, src + 16, ok ? 16 : 0);                                \
            cp16(d + 48, src + 24, ok ? 16 : 0);                                \
        }                                                                       \
        {   /* W: 64 rows x 64 halves; thread: row=tid>>2, seg=tid&3 (32B) */   \
            int kr = tid >> 2, seg = tid & 3;                                   \
            const __half* src = W + (size_t)((kc_)*64 + kr)*N + n0 + seg*16;    \
            uint32_t d = wb + (uint32_t)kr*(W64_ST*2) + (uint32_t)seg*32;       \
            cp16(d,      src,     16);                                          \
            cp16(d + 16, src + 8, 16);                                          \
        }                                                                       \
        CP_COMMIT();                                                            \
    } while (0)

    ISSUE_TILE64(0, 0);
    ISSUE_TILE64(1, 1);

    int a_row = lane & 15;
    int a_col = (lane >> 4) << 3;
    int b_krw = (lane & 7) + (((lane >> 4) & 1) << 3);
    int b_ncl = ((lane >> 3) & 1) << 3;

    for (int kc = 0; kc < nt; kc++) {
        int buf = kc % NSTAGE;
        if (kc == nt - 1) { CP_WAIT0(); } else { CP_WAIT1(); }
        __syncthreads();
        if (kc + 2 < nt) ISSUE_TILE64(kc + 2, (kc + 2) % NSTAGE);

        uint32_t ab = sbase + (uint32_t)buf * BUF64_BY;
        uint32_t wb = ab + A_BY;
#pragma unroll
        for (int ks = 0; ks < 4; ks++) {
            int k0 = ks * 16;
            uint32_t a[2][4], b[4][2];
#pragma unroll
            for (int mi = 0; mi < 2; mi++) {
                uint32_t addr = ab + (uint32_t)((wm0 + mi*16 + a_row)*A_ST + k0 + a_col)*2;
                ldsm_x4(a[mi][0], a[mi][1], a[mi][2], a[mi][3], addr);
            }
#pragma unroll
            for (int np = 0; np < 2; np++) {
                uint32_t addr = wb + (uint32_t)((k0 + b_krw)*W64_ST + wn0 + np*16 + b_ncl)*2;
                uint32_t r0, r1, r2, r3;
                ldsm_x4_t(r0, r1, r2, r3, addr);
                b[np*2][0]   = r0; b[np*2][1]   = r2;
                b[np*2+1][0] = r1; b[np*2+1][1] = r3;
            }
#pragma unroll
            for (int mi = 0; mi < 2; mi++)
#pragma unroll
                for (int ni = 0; ni < 4; ni++)
                    mma_f16(acc[mi][ni][0], acc[mi][ni][1], acc[mi][ni][2], acc[mi][ni][3],
                            a[mi][0], a[mi][1], a[mi][2], a[mi][3],
                            b[ni][0], b[ni][1]);
        }
    }
#undef ISSUE_TILE64

#pragma unroll
    for (int mi = 0; mi < 2; mi++) {
#pragma unroll
        for (int half_ = 0; half_ < 2; half_++) {
            int row = m0 + wm0 + mi*16 + g + half_*8;
            if (row >= M) continue;
#pragma unroll
            for (int ni = 0; ni < 4; ni++) {
                int col = n0 + wn0 + ni*8 + tig*2;
                float v0 = acc[mi][ni][half_*2]     + bias[col];
                float v1 = acc[mi][ni][half_*2 + 1] + bias[col+1];
                if (mode == 1) {
                    v0 = 0.5f*v0*(1.0f + erff(v0*0.70710678118654752f));
                    v1 = 0.5f*v1*(1.0f + erff(v1*0.70710678118654752f));
                    *(__half2*)((__half*)out + (size_t)row*N + col) =
                        __floats2half2_rn(v0, v1);
                } else if (mode == 4) {
                    *(__half2*)((__half*)out + (size_t)row*N + col) =
                        __floats2half2_rn(v0, v1);
                } else if (mode == 2) {
                    const float* rrow = resid + (size_t)row*N;
                    v0 += rrow[col];
                    v1 += rrow[col+1];
                    *(float2*)((float*)out + (size_t)row*N + col) = make_float2(v0, v1);
                } else if (mode == 3) {
                    int bb = row / SPLN, s = row % SPLN;
                    float* orow = (float*)out + ((size_t)bb*N_ + 1 + (size_t)s*4)*C_;
                    *(float2*)(orow + col) = make_float2(v0, v1);
                } else {
                    *(float2*)((float*)out + (size_t)row*N + col) = make_float2(v0, v1);
                }
            }
        }
    }
}

// ---------------- layernorm: warp per row ----------------
__global__ __launch_bounds__(256)
void ln_kernel(const float* __restrict__ in, __half* __restrict__ out,
               const float* __restrict__ gamma, const float* __restrict__ beta) {
    int warp = threadIdx.x >> 5, lane = threadIdx.x & 31;
    int row = blockIdx.x * 8 + warp;
    if (row >= M_ROWS) return;
    const float4* xr = (const float4*)(in + (size_t)row * C_);
    float4 v[6];
    float s = 0.f;
#pragma unroll
    for (int i = 0; i < 6; i++) {
        v[i] = xr[lane + i*32];
        s += v[i].x + v[i].y + v[i].z + v[i].w;
    }
#pragma unroll
    for (int o = 16; o; o >>= 1) s += __shfl_xor_sync(~0u, s, o);
    float mean = s * (1.0f / C_);
    float s2 = 0.f;
#pragma unroll
    for (int i = 0; i < 6; i++) {
        float a = v[i].x - mean, b = v[i].y - mean, c = v[i].z - mean, d = v[i].w - mean;
        s2 += a*a + b*b + c*c + d*d;
    }
#pragma unroll
    for (int o = 16; o; o >>= 1) s2 += __shfl_xor_sync(~0u, s2, o);
    float inv = rsqrtf(s2 * (1.0f / C_) + 1e-6f);
    __half2* orow = (__half2*)(out + (size_t)row * C_);
#pragma unroll
    for (int i = 0; i < 6; i++) {
        int c0 = (lane + i*32) * 4;
        float4 gm = *(const float4*)(gamma + c0);
        float4 bt = *(const float4*)(beta  + c0);
        orow[c0/2]     = __floats2half2_rn((v[i].x - mean)*inv*gm.x + bt.x,
                                           (v[i].y - mean)*inv*gm.y + bt.y);
        orow[c0/2 + 1] = __floats2half2_rn((v[i].z - mean)*inv*gm.z + bt.z,
                                           (v[i].w - mean)*inv*gm.w + bt.w);
    }
}

// ---------------- fp16 flash attention, 128 q-rows per CTA; row-0 scores exported ----------------
#define FA_SMEM 73728
__global__ __launch_bounds__(256)
void flash_attn(const __half* __restrict__ qkv, __half* __restrict__ obuf,
                float* __restrict__ srow_out) {
    extern __shared__ __half sh[];
    __half* Qs = sh;
    __half* Ps = sh + 27648;

    int bh = blockIdx.y;
    int b = bh / H_, h = bh % H_;
    int q0 = blockIdx.x * 128;
    int tid = threadIdx.x, warp = tid >> 5, lane = tid & 31;
    int g = lane >> 2, tig = lane & 3;
    const __half* base = qkv + (size_t)b * N_ * (3*C_) + h * D_;
    uint32_t sb = smem_u32(sh);

    {
        const uint4 z = make_uint4(0,0,0,0);
        for (int idx = tid; idx < 128*8; idx += 256) {
            int r = idx >> 3, c8 = idx & 7;
            int qr = q0 + r;
            uint4 v = z;
            if (qr < N_) v = *(const uint4*)(base + (size_t)qr*(3*C_) + c8*8);
            *(uint4*)(Qs + r*72 + c8*8) = v;
        }
    }

#define FA_ISSUE(kt_, buf_) do {                                              \
        uint32_t kb8 = sb + (uint32_t)(9216 + (buf_)*4608)*2u;                \
        uint32_t vb8 = sb + (uint32_t)(18432 + (buf_)*4608)*2u;               \
        _Pragma("unroll")                                                     \
        for (int it = 0; it < 2; it++) {                                      \
            int chunk = tid + it*256;                                         \
            int r = chunk >> 3, c8 = chunk & 7;                               \
            int kr = (kt_)*64 + r;                                            \
            int ok = (kr < N_);                                               \
            const __half* ksrc = base + (size_t)(ok ? kr : 0)*(3*C_) + C_   + c8*8; \
            const __half* vsrc = base + (size_t)(ok ? kr : 0)*(3*C_) + 2*C_ + c8*8; \
            cp16(kb8 + (uint32_t)(r*72 + c8*8)*2u, ksrc, ok ? 16 : 0);        \
            cp16(vb8 + (uint32_t)(r*72 + c8*8)*2u, vsrc, ok ? 16 : 0);        \
        }                                                                     \
        CP_COMMIT();                                                          \
    } while (0)

    FA_ISSUE(0, 0);
    FA_ISSUE(1, 1);

    float o[8][4];
#pragma unroll
    for (int i = 0; i < 8; i++) { o[i][0]=0.f; o[i][1]=0.f; o[i][2]=0.f; o[i][3]=0.f; }
    float mr0 = -INFINITY, mr1 = -INFINITY, l0 = 0.f, l1 = 0.f;

    __half* Pw = Ps + warp*16*72;

    int a_row = lane & 15;
    int a_col = (lane >> 4) << 3;
    int kb_nrow = (lane & 7) + ((lane >> 4) << 3);
    int kb_koff = ((lane >> 3) & 1) << 3;
    int vb_krw  = (lane & 7) + (((lane >> 4) & 1) << 3);
    int vb_ncl  = ((lane >> 3) & 1) << 3;

    uint32_t Qw_s = sb + (uint32_t)(warp*16*72)*2u;
    uint32_t Pw_s = sb + (uint32_t)(27648 + warp*16*72)*2u;

    bool cls_owner = (q0 == 0) && (warp == 0) && ((lane >> 2) == 0);

    for (int kt = 0; kt < 8; kt++) {
        int buf = kt & 1;
        if (kt == 7) { CP_WAIT0(); } else { CP_WAIT1(); }
        __syncthreads();
        uint32_t Kt_s = sb + (uint32_t)(9216  + buf*4608)*2u;
        uint32_t Vt_s = sb + (uint32_t)(18432 + buf*4608)*2u;

        float s[8][4];
#pragma unroll
        for (int i = 0; i < 8; i++) { s[i][0]=0.f; s[i][1]=0.f; s[i][2]=0.f; s[i][3]=0.f; }
#pragma unroll
        for (int ks = 0; ks < 4; ks++) {
            int k0 = ks * 16;
            uint32_t a0, a1, a2, a3;
            ldsm_x4(a0, a1, a2, a3, Qw_s + (uint32_t)(a_row*72 + k0 + a_col)*2u);
#pragma unroll
            for (int np = 0; np < 4; np++) {
                int nb = np * 16;
                uint32_t r0, r1, r2, r3;
                ldsm_x4(r0, r1, r2, r3, Kt_s + (uint32_t)((nb + kb_nrow)*72 + k0 + kb_koff)*2u);
                mma_f16(s[np*2][0],   s[np*2][1],   s[np*2][2],   s[np*2][3],   a0,a1,a2,a3, r0, r1);
                mma_f16(s[np*2+1][0], s[np*2+1][1], s[np*2+1][2], s[np*2+1][3], a0,a1,a2,a3, r2, r3);
            }
        }
        float mc0 = -INFINITY, mc1 = -INFINITY;
#pragma unroll
        for (int ni = 0; ni < 8; ni++) {
            int colb = kt*64 + ni*8 + 2*tig;
#pragma unroll
            for (int cc = 0; cc < 4; cc++) {
                float v = s[ni][cc] * 0.125f;
                if (colb + (cc & 1) >= N_) v = -INFINITY;
                s[ni][cc] = v;
                if (cc < 2) mc0 = fmaxf(mc0, v); else mc1 = fmaxf(mc1, v);
            }
        }
        if (cls_owner) {
            float* sr = srow_out + (size_t)bh*512 + kt*64;
#pragma unroll
            for (int ni = 0; ni < 8; ni++) {
                sr[ni*8 + 2*tig]     = s[ni][0];
                sr[ni*8 + 2*tig + 1] = s[ni][1];
            }
        }
        mc0 = fmaxf(mc0, __shfl_xor_sync(~0u, mc0, 1));
        mc0 = fmaxf(mc0, __shfl_xor_sync(~0u, mc0, 2));
        mc1 = fmaxf(mc1, __shfl_xor_sync(~0u, mc1, 1));
        mc1 = fmaxf(mc1, __shfl_xor_sync(~0u, mc1, 2));
        float mn0 = fmaxf(mr0, mc0), mn1 = fmaxf(mr1, mc1);
        float al0 = expf(mr0 - mn0), al1 = expf(mr1 - mn1);
        mr0 = mn0; mr1 = mn1;
        float ls0 = 0.f, ls1 = 0.f;
#pragma unroll
        for (int ni = 0; ni < 8; ni++) {
            float p0 = expf(s[ni][0] - mn0);
            float p1 = expf(s[ni][1] - mn0);
            float p2 = expf(s[ni][2] - mn1);
            float p3 = expf(s[ni][3] - mn1);
            s[ni][0]=p0; s[ni][1]=p1; s[ni][2]=p2; s[ni][3]=p3;
            ls0 += p0 + p1; ls1 += p2 + p3;
        }
        ls0 += __shfl_xor_sync(~0u, ls0, 1); ls0 += __shfl_xor_sync(~0u, ls0, 2);
        ls1 += __shfl_xor_sync(~0u, ls1, 1); ls1 += __shfl_xor_sync(~0u, ls1, 2);
        l0 = l0*al0 + ls0; l1 = l1*al1 + ls1;

        __syncwarp();
#pragma unroll
        for (int ni = 0; ni < 8; ni++) {
            *(__half2*)(Pw + g*72     + ni*8 + 2*tig) = __floats2half2_rn(s[ni][0], s[ni][1]);
            *(__half2*)(Pw + (g+8)*72 + ni*8 + 2*tig) = __floats2half2_rn(s[ni][2], s[ni][3]);
        }
#pragma unroll
        for (int ni = 0; ni < 8; ni++) {
            o[ni][0]*=al0; o[ni][1]*=al0; o[ni][2]*=al1; o[ni][3]*=al1;
        }
        __syncwarp();
#pragma unroll
        for (int ks = 0; ks < 4; ks++) {
            int k0 = ks * 16;
            uint32_t a0, a1, a2, a3;
            ldsm_x4(a0, a1, a2, a3, Pw_s + (uint32_t)(a_row*72 + k0 + a_col)*2u);
#pragma unroll
            for (int np = 0; np < 4; np++) {
                int nb = np * 16;
                uint32_t r0, r1, r2, r3;
                ldsm_x4_t(r0, r1, r2, r3, Vt_s + (uint32_t)((k0 + vb_krw)*72 + nb + vb_ncl)*2u);
                mma_f16(o[np*2][0],   o[np*2][1],   o[np*2][2],   o[np*2][3],   a0,a1,a2,a3, r0, r2);
                mma_f16(o[np*2+1][0], o[np*2+1][1], o[np*2+1][2], o[np*2+1][3], a0,a1,a2,a3, r1, r3);
            }
        }
        __syncthreads();
        if (kt + 2 < 8) FA_ISSUE(kt + 2, buf);
    }
#undef FA_ISSUE

    int r0 = q0 + warp*16 + g, r1 = r0 + 8;
    float inv0 = 1.f / l0, inv1 = 1.f / l1;
#pragma unroll
    for (int ni = 0; ni < 8; ni++) {
        int col = h*D_ + ni*8 + 2*tig;
        if (r0 < N_)
            *(__half2*)(obuf + ((size_t)b*N_ + r0)*C_ + col) =
                __floats2half2_rn(o[ni][0]*inv0, o[ni][1]*inv0);
        if (r1 < N_)
            *(__half2*)(obuf + ((size_t)b*N_ + r1)*C_ + col) =
                __floats2half2_rn(o[ni][2]*inv1, o[ni][3]*inv1);
    }
}

// ---------------- cls softmax over exported row-0 scores ----------------
__global__ __launch_bounds__(512)
void cls2_kernel(const float* __restrict__ srow, float* __restrict__ cls_acc) {
    __shared__ float red[16];
    int bh = blockIdx.x;
    int b = bh / H_;
    int tid = threadIdx.x, lane = tid & 31, warp = tid >> 5;
    float v = (tid < N_) ? srow[(size_t)bh*512 + tid] : -INFINITY;
    float m = v;
#pragma unroll
    for (int o = 16; o; o >>= 1) m = fmaxf(m, __shfl_xor_sync(~0u, m, o));
    if (lane == 0) red[warp] = m;
    __syncthreads();
    float M = red[0];
#pragma unroll
    for (int i = 1; i < 16; i++) M = fmaxf(M, red[i]);
    __syncthreads();
    float e = (tid < N_) ? expf(v - M) : 0.f;
    float t = e;
#pragma unroll
    for (int o = 16; o; o >>= 1) t += __shfl_xor_sync(~0u, t, o);
    if (lane == 0) red[warp] = t;
    __syncthreads();
    float L = 0.f;
#pragma unroll
    for (int i = 0; i < 16; i++) L += red[i];
    if (tid >= 1 && tid < N_)
        atomicAdd(&cls_acc[b*(N_-1) + tid - 1], e / (L * (float)H_));
}

// ---------------- glb EMA ----------------
__global__ void glb_kernel() {
    int i = blockIdx.x*blockDim.x + threadIdx.x;
    if (i < B_*(N_-1)) {
        g_glb[i] = 0.5f * g_glb[i] + 0.5f * g_cls[i];
        g_cls[i] = 0.f;
    }
}

// ---------------- glb output copy ----------------
__global__ void copy_glb_kernel(float* __restrict__ out) {
    int i = blockIdx.x*blockDim.x + threadIdx.x;
    if (i < B_*(N_-1)) out[(size_t)B_*N_*C_ + i] = g_glb[i];
}

// ---------------- launch ----------------
extern "C" void kernel_launch(void* const* d_in, const int* in_sizes, int n_in,
                              void* d_out, int out_size) {
    const float* x       = (const float*)d_in[0];
    const float* gattn   = (const float*)d_in[1];
    const float* split_w = (const float*)d_in[2];
    const float* split_b = (const float*)d_in[3];
    const float* ln1_g   = (const float*)d_in[4];
    const float* ln1_b   = (const float*)d_in[5];
    const float* qkv_w   = (const float*)d_in[6];
    const float* qkv_b   = (const float*)d_in[7];
    const float* proj_w  = (const float*)d_in[8];
    const float* proj_b  = (const float*)d_in[9];
    const float* ln2_g   = (const float*)d_in[10];
    const float* ln2_b   = (const float*)d_in[11];
    const float* fc1_w   = (const float*)d_in[12];
    const float* fc1_b   = (const float*)d_in[13];
    const float* fc2_w   = (const float*)d_in[14];
    const float* fc2_b   = (const float*)d_in[15];

    float *px, *pcls, *psrow;
    __half *ph, *pqkv, *po, *pmlp, *ptok;
    __half *pwsplit, *pwqkv, *pwproj, *pwfc1, *pwfc2;
    cudaGetSymbolAddress((void**)&px,   g_x);
    cudaGetSymbolAddress((void**)&ph,   g_h);
    cudaGetSymbolAddress((void**)&pqkv, g_qkv);
    cudaGetSymbolAddress((void**)&po,   g_o);
    cudaGetSymbolAddress((void**)&pmlp, g_mlp);
    cudaGetSymbolAddress((void**)&ptok, g_tok);
    cudaGetSymbolAddress((void**)&pcls, g_cls);
    cudaGetSymbolAddress((void**)&psrow, g_srow);
    cudaGetSymbolAddress((void**)&pwsplit, g_wsplit);
    cudaGetSymbolAddress((void**)&pwqkv,   g_wqkv);
    cudaGetSymbolAddress((void**)&pwproj,  g_wproj);
    cudaGetSymbolAddress((void**)&pwfc1,   g_wfc1);
    cudaGetSymbolAddress((void**)&pwfc2,   g_wfc2);

    cudaFuncSetAttribute(gemm_h,     cudaFuncAttributeMaxDynamicSharedMemorySize, GEMM_SMEM);
    cudaFuncSetAttribute(gemm_h64,   cudaFuncAttributeMaxDynamicSharedMemorySize, GEMM64_SMEM);
    cudaFuncSetAttribute(flash_attn, cudaFuncAttributeMaxDynamicSharedMemorySize, FA_SMEM);

    wconv5_kernel<<<2048, 256>>>(split_w, pwsplit, SW_SZ,
                                 qkv_w,   pwqkv,   L_*QW_SZ,
                                 proj_w,  pwproj,  L_*PW_SZ,
                                 fc1_w,   pwfc1,   L_*F1_SZ,
                                 fc2_w,   pwfc2,   L_*F2_SZ);
    sort_kernel<<<B_, 256>>>(gattn);
    gather_kernel<<<B_*197, 256>>>(x);
    init_kernel<<<(B_*(N_-1) + 255)/256, 256>>>();

    {   // split GEMM  M=1568, N=3072, K=768 (128x64 tiles: 48x13=624 CTAs)
        dim3 grid((4*C_)/64, (B_*SPLN + 127)/128);
        gemm_h64<<<grid, 256, GEMM64_SMEM>>>(ptok, pwsplit, split_b, nullptr, px,
                                             B_*SPLN, 4*C_, C_, 3);
    }

    for (int l = 0; l < L_; l++) {
        const float* l1g = ln1_g + l*C_;
        const float* l1b = ln1_b + l*C_;
        const __half* qw = pwqkv + (size_t)l*QW_SZ;
        const float* qb  = qkv_b + l*3*C_;
        const __half* pw = pwproj + (size_t)l*PW_SZ;
        const float* pb  = proj_b + l*C_;
        const float* l2g = ln2_g + l*C_;
        const float* l2b = ln2_b + l*C_;
        const __half* w1 = pwfc1 + (size_t)l*F1_SZ;
        const float* b1  = fc1_b + l*HM_;
        const __half* w2 = pwfc2 + (size_t)l*F2_SZ;
        const float* b2  = fc2_b + l*C_;

        ln_kernel<<<(M_ROWS + 7)/8, 256>>>(px, ph, l1g, l1b);

        { dim3 grid((3*C_)/128, (M_ROWS + 127)/128);
          gemm_h<<<grid, 256, GEMM_SMEM>>>(ph, qw, qb, nullptr, pqkv, M_ROWS, 3*C_, C_, 4); }

        { dim3 grid(4, B_*H_);
          flash_attn<<<grid, 256, FA_SMEM>>>(pqkv, po, psrow); }

        cls2_kernel<<<B_*H_, 512>>>(psrow, pcls);

        glb_kernel<<<(B_*(N_-1) + 255)/256, 256>>>();

        {   // proj: N=768 -> 128x64 tiles (12x62=744 CTAs)
            dim3 grid(C_/64, (M_ROWS + 127)/128);
            gemm_h64<<<grid, 256, GEMM64_SMEM>>>(po, pw, pb, px, px, M_ROWS, C_, C_, 2);
        }

        ln_kernel<<<(M_ROWS + 7)/8, 256>>>(px, ph, l2g, l2b);

        { dim3 grid(HM_/128, (M_ROWS + 127)/128);
          gemm_h<<<grid, 256, GEMM_SMEM>>>(ph, w1, b1, nullptr, pmlp, M_ROWS, HM_, C_, 1); }

        {   // fc2: N=768 -> 128x64 tiles; final layer writes x into d_out
            float* xdst = (l == L_ - 1) ? (float*)d_out : px;
            dim3 grid(C_/64, (M_ROWS + 127)/128);
            gemm_h64<<<grid, 256, GEMM64_SMEM>>>(pmlp, w2, b2, px, xdst, M_ROWS, C_, HM_, 2);
        }
    }

    copy_glb_kernel<<<(B_*(N_-1) + 255)/256, 256>>>((float*)d_out);
}

// round 14
// speedup vs baseline: 1.0506x; 1.0472x over previous
#include <cuda_runtime.h>
#include <cuda_fp16.h>
#include <math.h>
#include <stdint.h>

// ---------------- problem constants ----------------
#define B_    16
#define NTOK  196
#define SPLN  98
#define N_    491          // 1 + 98*4 + 98
#define C_    768
#define HM_   3072
#define H_    12
#define D_    64
#define L_    4
#define M_ROWS (B_*N_)     // 7856

// weight sizes
#define SW_SZ   (C_*4*C_)
#define QW_SZ   (C_*3*C_)
#define PW_SZ   (C_*C_)
#define F1_SZ   (C_*HM_)
#define F2_SZ   (HM_*C_)

// ---------------- device scratch ----------------
__device__ float  g_x   [B_*N_*C_];
__device__ __half g_h   [B_*N_*C_];
__device__ __half g_qkv [B_*N_*3*C_];
__device__ __half g_o   [B_*N_*C_];
__device__ __half g_mlp [B_*N_*HM_];
__device__ __half g_tok [B_*SPLN*C_];
__device__ int    g_ord [B_*NTOK];
__device__ float  g_glb [B_*(N_-1)];
__device__ float  g_cls [B_*(N_-1)];
__device__ float  g_srow[B_*H_*512];
__device__ float  g_part[2*(size_t)M_ROWS*C_];   // split-K partials
// fp16 weights
__device__ __half g_wsplit[SW_SZ];
__device__ __half g_wqkv  [L_*QW_SZ];
__device__ __half g_wproj [L_*PW_SZ];
__device__ __half g_wfc1  [L_*F1_SZ];
__device__ __half g_wfc2  [L_*F2_SZ];

// ---------------- helpers ----------------
__device__ __forceinline__ uint32_t smem_u32(const void* p) {
    uint32_t a;
    asm("{ .reg .u64 t; cvta.to.shared.u64 t, %1; cvt.u32.u64 %0, t; }" : "=r"(a) : "l"(p));
    return a;
}
__device__ __forceinline__ void mma_f16(float& c0, float& c1, float& c2, float& c3,
                                        uint32_t a0, uint32_t a1, uint32_t a2, uint32_t a3,
                                        uint32_t b0, uint32_t b1) {
    asm volatile("mma.sync.aligned.m16n8k16.row.col.f32.f16.f16.f32 "
                 "{%0,%1,%2,%3}, {%4,%5,%6,%7}, {%8,%9}, {%0,%1,%2,%3};"
                 : "+f"(c0), "+f"(c1), "+f"(c2), "+f"(c3)
                 : "r"(a0), "r"(a1), "r"(a2), "r"(a3), "r"(b0), "r"(b1));
}
__device__ __forceinline__ void ldsm_x4(uint32_t& r0, uint32_t& r1, uint32_t& r2, uint32_t& r3,
                                        uint32_t addr) {
    asm volatile("ldmatrix.sync.aligned.m8n8.x4.shared.b16 {%0,%1,%2,%3}, [%4];"
                 : "=r"(r0), "=r"(r1), "=r"(r2), "=r"(r3) : "r"(addr));
}
__device__ __forceinline__ void ldsm_x4_t(uint32_t& r0, uint32_t& r1, uint32_t& r2, uint32_t& r3,
                                          uint32_t addr) {
    asm volatile("ldmatrix.sync.aligned.m8n8.x4.trans.shared.b16 {%0,%1,%2,%3}, [%4];"
                 : "=r"(r0), "=r"(r1), "=r"(r2), "=r"(r3) : "r"(addr));
}
__device__ __forceinline__ void cp16(uint32_t dst, const void* src, int sz) {
    asm volatile("cp.async.cg.shared.global [%0], [%1], 16, %2;"
                 :: "r"(dst), "l"(src), "r"(sz) : "memory");
}
#define CP_COMMIT() asm volatile("cp.async.commit_group;" ::: "memory")
#define CP_WAIT1()  asm volatile("cp.async.wait_group 1;" ::: "memory")
#define CP_WAIT0()  asm volatile("cp.async.wait_group 0;" ::: "memory")

// ---------------- fused weight convert (5 tensors) ----------------
__global__ void wconv5_kernel(const float* a0, __half* b0, int n0,
                              const float* a1, __half* b1, int n1,
                              const float* a2, __half* b2, int n2,
                              const float* a3, __half* b3, int n3,
                              const float* a4, __half* b4, int n4) {
    int stride = gridDim.x * blockDim.x;
    int tot = n0 + n1 + n2 + n3 + n4;
    for (int i = blockIdx.x*blockDim.x + threadIdx.x; i < tot; i += stride) {
        int j = i;
        const float* s; __half* d;
        if (j < n0) { s = a0; d = b0; }
        else { j -= n0;
            if (j < n1) { s = a1; d = b1; }
            else { j -= n1;
                if (j < n2) { s = a2; d = b2; }
                else { j -= n2;
                    if (j < n3) { s = a3; d = b3; }
                    else { j -= n3; s = a4; d = b4; }
                }
            }
        }
        d[j] = __float2half_rn(s[j]);
    }
}

// ---------------- sort ----------------
__global__ void sort_kernel(const float* __restrict__ attn) {
    __shared__ float sv[256];
    __shared__ int   si[256];
    int b = blockIdx.x, t = threadIdx.x;
    sv[t] = (t < NTOK) ? attn[b*NTOK + t] : -INFINITY;
    si[t] = t;
    __syncthreads();
    for (int k = 2; k <= 256; k <<= 1) {
        for (int j = k >> 1; j > 0; j >>= 1) {
            int ix = t ^ j;
            if (ix > t) {
                float v1 = sv[t], v2 = sv[ix];
                int   i1 = si[t], i2 = si[ix];
                bool before = (v1 > v2) || (v1 == v2 && i1 < i2);
                bool doswap = ((t & k) == 0) ? (!before) : before;
                if (doswap) { sv[t]=v2; sv[ix]=v1; si[t]=i2; si[ix]=i1; }
            }
            __syncthreads();
        }
    }
    if (t < NTOK) g_ord[b*NTOK + t] = si[t];
}

// ---------------- gather ----------------
__global__ void gather_kernel(const float* __restrict__ xin) {
    int blk = blockIdx.x;
    int b = blk / 197, r = blk % 197;
    int t = threadIdx.x;
    if (r == 0) {
        const float* srow = xin + (size_t)b*197*C_;
        float* drow = g_x + (size_t)b*N_*C_;
        drow[t] = srow[t]; drow[t+256] = srow[t+256]; drow[t+512] = srow[t+512];
    } else if (r <= SPLN) {
        int i = r - 1;
        int ord = g_ord[b*NTOK + i];
        const float* srow = xin + ((size_t)b*197 + 1 + ord)*C_;
        __half* drow = g_tok + ((size_t)b*SPLN + i)*C_;
        drow[t]     = __float2half_rn(srow[t]);
        drow[t+256] = __float2half_rn(srow[t+256]);
        drow[t+512] = __float2half_rn(srow[t+512]);
    } else {
        int i = r - 1 - SPLN;
        int ord = g_ord[b*NTOK + SPLN + i];
        const float* srow = xin + ((size_t)b*197 + 1 + ord)*C_;
        float* drow = g_x + ((size_t)b*N_ + 1 + SPLN*4 + i)*C_;
        drow[t] = srow[t]; drow[t+256] = srow[t+256]; drow[t+512] = srow[t+512];
    }
}

__global__ void init_kernel() {
    int i = blockIdx.x*blockDim.x + threadIdx.x;
    if (i < B_*(N_-1)) { g_glb[i] = 0.f; g_cls[i] = 0.f; }
}

// =============== fp16 GEMM 128x128 tile, BK=64, warp 64x32, 3-stage cp.async ===============
// modes: 0 bias->f32 | 1 bias+gelu->HALF | 2 bias+residual->f32 | 3 bias+split-remap->f32
//        4 bias->HALF | 5 split-K partial (no bias) -> float part[z]
#define A_ST 72
#define W_ST 136
#define A_BY (128*A_ST*2)
#define W_BY (64*W_ST*2)
#define BUF_BY (A_BY + W_BY)
#define NSTAGE 3
#define GEMM_SMEM (NSTAGE*BUF_BY)

__global__ __launch_bounds__(256, 2)
void gemm_h(const __half* __restrict__ A, const __half* __restrict__ W,
            const float* __restrict__ bias, const float* __restrict__ resid,
            void* __restrict__ out, int M, int N, int K, int mode) {
    extern __shared__ char smc[];
    int tid  = threadIdx.x;
    int m0   = blockIdx.y * 128, n0 = blockIdx.x * 128;
    int z    = blockIdx.z;
    int warp = tid >> 5, lane = tid & 31;
    int g    = lane >> 2, tig = lane & 3;
    int wm0  = (warp >> 2) * 64;
    int wn0  = (warp & 3) * 32;

    uint32_t sbase = smem_u32(smc);

    float acc[4][4][4];
#pragma unroll
    for (int i = 0; i < 4; i++)
#pragma unroll
        for (int j = 0; j < 4; j++)
#pragma unroll
            for (int c = 0; c < 4; c++) acc[i][j][c] = 0.f;

    int koff = 0, nt;
    if (mode == 5) { koff = z * (K >> 1); nt = (K >> 1) >> 6; }
    else           { nt = K >> 6; }

#define ISSUE_TILE(kc_, buf_) do {                                              \
        uint32_t ab = sbase + (uint32_t)(buf_) * BUF_BY;                        \
        uint32_t wb = ab + A_BY;                                               \
        {                                                                       \
            int row = tid >> 1, c = tid & 1;                                    \
            int gr = m0 + row;                                                  \
            int ok = (gr < M);                                                  \
            const __half* src = A + (size_t)(ok ? gr : 0)*K + koff + (kc_)*64 + c*32; \
            uint32_t d = ab + (uint32_t)row*(A_ST*2) + (uint32_t)c*64;          \
            cp16(d,      src,      ok ? 16 : 0);                                \
            cp16(d + 16, src + 8,  ok ? 16 : 0);                                \
            cp16(d + 32, src + 16, ok ? 16 : 0);                                \
            cp16(d + 48, src + 24, ok ? 16 : 0);                                \
        }                                                                       \
        {                                                                       \
            int kr = tid >> 3, seg = tid & 7;                                   \
            _Pragma("unroll")                                                   \
            for (int rr = 0; rr < 2; rr++) {                                    \
                int r = kr + rr*32;                                             \
                const __half* src = W + (size_t)(koff + (kc_)*64 + r)*N + n0 + seg*16; \
                uint32_t d = wb + (uint32_t)r*(W_ST*2) + (uint32_t)seg*32;      \
                cp16(d,      src,     16);                                      \
                cp16(d + 16, src + 8, 16);                                      \
            }                                                                   \
        }                                                                       \
        CP_COMMIT();                                                            \
    } while (0)

    ISSUE_TILE(0, 0);
    if (nt > 1) ISSUE_TILE(1, 1);

    int a_row = lane & 15;
    int a_col = (lane >> 4) << 3;
    int b_krw = (lane & 7) + (((lane >> 4) & 1) << 3);
    int b_ncl = ((lane >> 3) & 1) << 3;

    for (int kc = 0; kc < nt; kc++) {
        int buf = kc % NSTAGE;
        if (kc == nt - 1) { CP_WAIT0(); } else { CP_WAIT1(); }
        __syncthreads();
        if (kc + 2 < nt) ISSUE_TILE(kc + 2, (kc + 2) % NSTAGE);

        uint32_t ab = sbase + (uint32_t)buf * BUF_BY;
        uint32_t wb = ab + A_BY;
#pragma unroll
        for (int ks = 0; ks < 4; ks++) {
            int k0 = ks * 16;
            uint32_t a[4][4], b[4][2];
#pragma unroll
            for (int mi = 0; mi < 4; mi++) {
                uint32_t addr = ab + (uint32_t)((wm0 + mi*16 + a_row)*A_ST + k0 + a_col)*2;
                ldsm_x4(a[mi][0], a[mi][1], a[mi][2], a[mi][3], addr);
            }
#pragma unroll
            for (int np = 0; np < 2; np++) {
                uint32_t addr = wb + (uint32_t)((k0 + b_krw)*W_ST + wn0 + np*16 + b_ncl)*2;
                uint32_t r0, r1, r2, r3;
                ldsm_x4_t(r0, r1, r2, r3, addr);
                b[np*2][0]   = r0; b[np*2][1]   = r2;
                b[np*2+1][0] = r1; b[np*2+1][1] = r3;
            }
#pragma unroll
            for (int mi = 0; mi < 4; mi++)
#pragma unroll
                for (int ni = 0; ni < 4; ni++)
                    mma_f16(acc[mi][ni][0], acc[mi][ni][1], acc[mi][ni][2], acc[mi][ni][3],
                            a[mi][0], a[mi][1], a[mi][2], a[mi][3],
                            b[ni][0], b[ni][1]);
        }
    }
#undef ISSUE_TILE

#pragma unroll
    for (int mi = 0; mi < 4; mi++) {
#pragma unroll
        for (int half_ = 0; half_ < 2; half_++) {
            int row = m0 + wm0 + mi*16 + g + half_*8;
            if (row >= M) continue;
#pragma unroll
            for (int ni = 0; ni < 4; ni++) {
                int col = n0 + wn0 + ni*8 + tig*2;
                if (mode == 5) {
                    float* po = (float*)out + (size_t)z*M_ROWS*C_ + (size_t)row*N + col;
                    *(float2*)po = make_float2(acc[mi][ni][half_*2], acc[mi][ni][half_*2 + 1]);
                    continue;
                }
                float v0 = acc[mi][ni][half_*2]     + bias[col];
                float v1 = acc[mi][ni][half_*2 + 1] + bias[col+1];
                if (mode == 1) {
                    v0 = 0.5f*v0*(1.0f + erff(v0*0.70710678118654752f));
                    v1 = 0.5f*v1*(1.0f + erff(v1*0.70710678118654752f));
                    *(__half2*)((__half*)out + (size_t)row*N + col) =
                        __floats2half2_rn(v0, v1);
                } else if (mode == 4) {
                    *(__half2*)((__half*)out + (size_t)row*N + col) =
                        __floats2half2_rn(v0, v1);
                } else if (mode == 2) {
                    const float* rrow = resid + (size_t)row*N;
                    v0 += rrow[col];
                    v1 += rrow[col+1];
                    *(float2*)((float*)out + (size_t)row*N + col) = make_float2(v0, v1);
                } else if (mode == 3) {
                    int bb = row / SPLN, s = row % SPLN;
                    float* orow = (float*)out + ((size_t)bb*N_ + 1 + (size_t)s*4)*C_;
                    *(float2*)(orow + col) = make_float2(v0, v1);
                } else {
                    *(float2*)((float*)out + (size_t)row*N + col) = make_float2(v0, v1);
                }
            }
        }
    }
}

// ---------------- layernorm: warp per row ----------------
__global__ __launch_bounds__(256)
void ln_kernel(const float* __restrict__ in, __half* __restrict__ out,
               const float* __restrict__ gamma, const float* __restrict__ beta) {
    int warp = threadIdx.x >> 5, lane = threadIdx.x & 31;
    int row = blockIdx.x * 8 + warp;
    if (row >= M_ROWS) return;
    const float4* xr = (const float4*)(in + (size_t)row * C_);
    float4 v[6];
    float s = 0.f;
#pragma unroll
    for (int i = 0; i < 6; i++) {
        v[i] = xr[lane + i*32];
        s += v[i].x + v[i].y + v[i].z + v[i].w;
    }
#pragma unroll
    for (int o = 16; o; o >>= 1) s += __shfl_xor_sync(~0u, s, o);
    float mean = s * (1.0f / C_);
    float s2 = 0.f;
#pragma unroll
    for (int i = 0; i < 6; i++) {
        float a = v[i].x - mean, b = v[i].y - mean, c = v[i].z - mean, d = v[i].w - mean;
        s2 += a*a + b*b + c*c + d*d;
    }
#pragma unroll
    for (int o = 16; o; o >>= 1) s2 += __shfl_xor_sync(~0u, s2, o);
    float inv = rsqrtf(s2 * (1.0f / C_) + 1e-6f);
    __half2* orow = (__half2*)(out + (size_t)row * C_);
#pragma unroll
    for (int i = 0; i < 6; i++) {
        int c0 = (lane + i*32) * 4;
        float4 gm = *(const float4*)(gamma + c0);
        float4 bt = *(const float4*)(beta  + c0);
        orow[c0/2]     = __floats2half2_rn((v[i].x - mean)*inv*gm.x + bt.x,
                                           (v[i].y - mean)*inv*gm.y + bt.y);
        orow[c0/2 + 1] = __floats2half2_rn((v[i].z - mean)*inv*gm.z + bt.z,
                                           (v[i].w - mean)*inv*gm.w + bt.w);
    }
}

// ---------------- LN with fused split-K reduction: x = x + p0 + p1 + bias; h = LN(x) --------
__global__ __launch_bounds__(256)
void ln_red_kernel(const float* __restrict__ part, const float* __restrict__ bias,
                   float* __restrict__ x, __half* __restrict__ hout,
                   const float* __restrict__ gamma, const float* __restrict__ beta) {
    int warp = threadIdx.x >> 5, lane = threadIdx.x & 31;
    int row = blockIdx.x * 8 + warp;
    if (row >= M_ROWS) return;
    float4* xr = (float4*)(x + (size_t)row * C_);
    const float4* p0 = (const float4*)(part + (size_t)row * C_);
    const float4* p1 = (const float4*)(part + (size_t)M_ROWS*C_ + (size_t)row * C_);
    float4 v[6];
    float s = 0.f;
#pragma unroll
    for (int i = 0; i < 6; i++) {
        int idx = lane + i*32;
        float4 xv = xr[idx];
        float4 a = p0[idx];
        float4 b = p1[idx];
        float4 bb = *(const float4*)(bias + idx*4);
        v[i].x = xv.x + a.x + b.x + bb.x;
        v[i].y = xv.y + a.y + b.y + bb.y;
        v[i].z = xv.z + a.z + b.z + bb.z;
        v[i].w = xv.w + a.w + b.w + bb.w;
        s += v[i].x + v[i].y + v[i].z + v[i].w;
    }
#pragma unroll
    for (int o = 16; o; o >>= 1) s += __shfl_xor_sync(~0u, s, o);
    float mean = s * (1.0f / C_);
    float s2 = 0.f;
#pragma unroll
    for (int i = 0; i < 6; i++) {
        float a = v[i].x - mean, b = v[i].y - mean, c = v[i].z - mean, d = v[i].w - mean;
        s2 += a*a + b*b + c*c + d*d;
    }
#pragma unroll
    for (int o = 16; o; o >>= 1) s2 += __shfl_xor_sync(~0u, s2, o);
    float inv = rsqrtf(s2 * (1.0f / C_) + 1e-6f);
    __half2* orow = (__half2*)(hout + (size_t)row * C_);
#pragma unroll
    for (int i = 0; i < 6; i++) {
        int idx = lane + i*32;
        int c0 = idx * 4;
        xr[idx] = v[i];
        float4 gm = *(const float4*)(gamma + c0);
        float4 bt = *(const float4*)(beta  + c0);
        orow[c0/2]     = __floats2half2_rn((v[i].x - mean)*inv*gm.x + bt.x,
                                           (v[i].y - mean)*inv*gm.y + bt.y);
        orow[c0/2 + 1] = __floats2half2_rn((v[i].z - mean)*inv*gm.z + bt.z,
                                           (v[i].w - mean)*inv*gm.w + bt.w);
    }
}

// ---------------- fp16 flash attention, 128 q-rows per CTA; row-0 scores exported ----------------
#define FA_SMEM 73728
__global__ __launch_bounds__(256)
void flash_attn(const __half* __restrict__ qkv, __half* __restrict__ obuf,
                float* __restrict__ srow_out) {
    extern __shared__ __half sh[];
    __half* Qs = sh;
    __half* Ps = sh + 27648;

    int bh = blockIdx.y;
    int b = bh / H_, h = bh % H_;
    int q0 = blockIdx.x * 128;
    int tid = threadIdx.x, warp = tid >> 5, lane = tid & 31;
    int g = lane >> 2, tig = lane & 3;
    const __half* base = qkv + (size_t)b * N_ * (3*C_) + h * D_;
    uint32_t sb = smem_u32(sh);

    {
        const uint4 z = make_uint4(0,0,0,0);
        for (int idx = tid; idx < 128*8; idx += 256) {
            int r = idx >> 3, c8 = idx & 7;
            int qr = q0 + r;
            uint4 v = z;
            if (qr < N_) v = *(const uint4*)(base + (size_t)qr*(3*C_) + c8*8);
            *(uint4*)(Qs + r*72 + c8*8) = v;
        }
    }

#define FA_ISSUE(kt_, buf_) do {                                              \
        uint32_t kb8 = sb + (uint32_t)(9216 + (buf_)*4608)*2u;                \
        uint32_t vb8 = sb + (uint32_t)(18432 + (buf_)*4608)*2u;               \
        _Pragma("unroll")                                                     \
        for (int it = 0; it < 2; it++) {                                      \
            int chunk = tid + it*256;                                         \
            int r = chunk >> 3, c8 = chunk & 7;                               \
            int kr = (kt_)*64 + r;                                            \
            int ok = (kr < N_);                                               \
            const __half* ksrc = base + (size_t)(ok ? kr : 0)*(3*C_) + C_   + c8*8; \
            const __half* vsrc = base + (size_t)(ok ? kr : 0)*(3*C_) + 2*C_ + c8*8; \
            cp16(kb8 + (uint32_t)(r*72 + c8*8)*2u, ksrc, ok ? 16 : 0);        \
            cp16(vb8 + (uint32_t)(r*72 + c8*8)*2u, vsrc, ok ? 16 : 0);        \
        }                                                                     \
        CP_COMMIT();                                                          \
    } while (0)

    FA_ISSUE(0, 0);
    FA_ISSUE(1, 1);

    float o[8][4];
#pragma unroll
    for (int i = 0; i < 8; i++) { o[i][0]=0.f; o[i][1]=0.f; o[i][2]=0.f; o[i][3]=0.f; }
    float mr0 = -INFINITY, mr1 = -INFINITY, l0 = 0.f, l1 = 0.f;

    __half* Pw = Ps + warp*16*72;

    int a_row = lane & 15;
    int a_col = (lane >> 4) << 3;
    int kb_nrow = (lane & 7) + ((lane >> 4) << 3);
    int kb_koff = ((lane >> 3) & 1) << 3;
    int vb_krw  = (lane & 7) + (((lane >> 4) & 1) << 3);
    int vb_ncl  = ((lane >> 3) & 1) << 3;

    uint32_t Qw_s = sb + (uint32_t)(warp*16*72)*2u;
    uint32_t Pw_s = sb + (uint32_t)(27648 + warp*16*72)*2u;

    bool cls_owner = (q0 == 0) && (warp == 0) && ((lane >> 2) == 0);

    for (int kt = 0; kt < 8; kt++) {
        int buf = kt & 1;
        if (kt == 7) { CP_WAIT0(); } else { CP_WAIT1(); }
        __syncthreads();
        uint32_t Kt_s = sb + (uint32_t)(9216  + buf*4608)*2u;
        uint32_t Vt_s = sb + (uint32_t)(18432 + buf*4608)*2u;

        float s[8][4];
#pragma unroll
        for (int i = 0; i < 8; i++) { s[i][0]=0.f; s[i][1]=0.f; s[i][2]=0.f; s[i][3]=0.f; }
#pragma unroll
        for (int ks = 0; ks < 4; ks++) {
            int k0 = ks * 16;
            uint32_t a0, a1, a2, a3;
            ldsm_x4(a0, a1, a2, a3, Qw_s + (uint32_t)(a_row*72 + k0 + a_col)*2u);
#pragma unroll
            for (int np = 0; np < 4; np++) {
                int nb = np * 16;
                uint32_t r0, r1, r2, r3;
                ldsm_x4(r0, r1, r2, r3, Kt_s + (uint32_t)((nb + kb_nrow)*72 + k0 + kb_koff)*2u);
                mma_f16(s[np*2][0],   s[np*2][1],   s[np*2][2],   s[np*2][3],   a0,a1,a2,a3, r0, r1);
                mma_f16(s[np*2+1][0], s[np*2+1][1], s[np*2+1][2], s[np*2+1][3], a0,a1,a2,a3, r2, r3);
            }
        }
        float mc0 = -INFINITY, mc1 = -INFINITY;
#pragma unroll
        for (int ni = 0; ni < 8; ni++) {
            int colb = kt*64 + ni*8 + 2*tig;
#pragma unroll
            for (int cc = 0; cc < 4; cc++) {
                float v = s[ni][cc] * 0.125f;
                if (colb + (cc & 1) >= N_) v = -INFINITY;
                s[ni][cc] = v;
                if (cc < 2) mc0 = fmaxf(mc0, v); else mc1 = fmaxf(mc1, v);
            }
        }
        if (cls_owner) {
            float* sr = srow_out + (size_t)bh*512 + kt*64;
#pragma unroll
            for (int ni = 0; ni < 8; ni++) {
                sr[ni*8 + 2*tig]     = s[ni][0];
                sr[ni*8 + 2*tig + 1] = s[ni][1];
            }
        }
        mc0 = fmaxf(mc0, __shfl_xor_sync(~0u, mc0, 1));
        mc0 = fmaxf(mc0, __shfl_xor_sync(~0u, mc0, 2));
        mc1 = fmaxf(mc1, __shfl_xor_sync(~0u, mc1, 1));
        mc1 = fmaxf(mc1, __shfl_xor_sync(~0u, mc1, 2));
        float mn0 = fmaxf(mr0, mc0), mn1 = fmaxf(mr1, mc1);
        float al0 = expf(mr0 - mn0), al1 = expf(mr1 - mn1);
        mr0 = mn0; mr1 = mn1;
        float ls0 = 0.f, ls1 = 0.f;
#pragma unroll
        for (int ni = 0; ni < 8; ni++) {
            float p0 = expf(s[ni][0] - mn0);
            float p1 = expf(s[ni][1] - mn0);
            float p2 = expf(s[ni][2] - mn1);
            float p3 = expf(s[ni][3] - mn1);
            s[ni][0]=p0; s[ni][1]=p1; s[ni][2]=p2; s[ni][3]=p3;
            ls0 += p0 + p1; ls1 += p2 + p3;
        }
        ls0 += __shfl_xor_sync(~0u, ls0, 1); ls0 += __shfl_xor_sync(~0u, ls0, 2);
        ls1 += __shfl_xor_sync(~0u, ls1, 1); ls1 += __shfl_xor_sync(~0u, ls1, 2);
        l0 = l0*al0 + ls0; l1 = l1*al1 + ls1;

        __syncwarp();
#pragma unroll
        for (int ni = 0; ni < 8; ni++) {
            *(__half2*)(Pw + g*72     + ni*8 + 2*tig) = __floats2half2_rn(s[ni][0], s[ni][1]);
            *(__half2*)(Pw + (g+8)*72 + ni*8 + 2*tig) = __floats2half2_rn(s[ni][2], s[ni][3]);
        }
#pragma unroll
        for (int ni = 0; ni < 8; ni++) {
            o[ni][0]*=al0; o[ni][1]*=al0; o[ni][2]*=al1; o[ni][3]*=al1;
        }
        __syncwarp();
#pragma unroll
        for (int ks = 0; ks < 4; ks++) {
            int k0 = ks * 16;
            uint32_t a0, a1, a2, a3;
            ldsm_x4(a0, a1, a2, a3, Pw_s + (uint32_t)(a_row*72 + k0 + a_col)*2u);
#pragma unroll
            for (int np = 0; np < 4; np++) {
                int nb = np * 16;
                uint32_t r0, r1, r2, r3;
                ldsm_x4_t(r0, r1, r2, r3, Vt_s + (uint32_t)((k0 + vb_krw)*72 + nb + vb_ncl)*2u);
                mma_f16(o[np*2][0],   o[np*2][1],   o[np*2][2],   o[np*2][3],   a0,a1,a2,a3, r0, r2);
                mma_f16(o[np*2+1][0], o[np*2+1][1], o[np*2+1][2], o[np*2+1][3], a0,a1,a2,a3, r1, r3);
            }
        }
        __syncthreads();
        if (kt + 2 < 8) FA_ISSUE(kt + 2, buf);
    }
#undef FA_ISSUE

    int r0 = q0 + warp*16 + g, r1 = r0 + 8;
    float inv0 = 1.f / l0, inv1 = 1.f / l1;
#pragma unroll
    for (int ni = 0; ni < 8; ni++) {
        int col = h*D_ + ni*8 + 2*tig;
        if (r0 < N_)
            *(__half2*)(obuf + ((size_t)b*N_ + r0)*C_ + col) =
                __floats2half2_rn(o[ni][0]*inv0, o[ni][1]*inv0);
        if (r1 < N_)
            *(__half2*)(obuf + ((size_t)b*N_ + r1)*C_ + col) =
                __floats2half2_rn(o[ni][2]*inv1, o[ni][3]*inv1);
    }
}

// ---------------- cls softmax over exported row-0 scores ----------------
__global__ __launch_bounds__(512)
void cls2_kernel(const float* __restrict__ srow, float* __restrict__ cls_acc) {
    __shared__ float red[16];
    int bh = blockIdx.x;
    int b = bh / H_;
    int tid = threadIdx.x, lane = tid & 31, warp = tid >> 5;
    float v = (tid < N_) ? srow[(size_t)bh*512 + tid] : -INFINITY;
    float m = v;
#pragma unroll
    for (int o = 16; o; o >>= 1) m = fmaxf(m, __shfl_xor_sync(~0u, m, o));
    if (lane == 0) red[warp] = m;
    __syncthreads();
    float M = red[0];
#pragma unroll
    for (int i = 1; i < 16; i++) M = fmaxf(M, red[i]);
    __syncthreads();
    float e = (tid < N_) ? expf(v - M) : 0.f;
    float t = e;
#pragma unroll
    for (int o = 16; o; o >>= 1) t += __shfl_xor_sync(~0u, t, o);
    if (lane == 0) red[warp] = t;
    __syncthreads();
    float L = 0.f;
#pragma unroll
    for (int i = 0; i < 16; i++) L += red[i];
    if (tid >= 1 && tid < N_)
        atomicAdd(&cls_acc[b*(N_-1) + tid - 1], e / (L * (float)H_));
}

// ---------------- glb EMA ----------------
__global__ void glb_kernel() {
    int i = blockIdx.x*blockDim.x + threadIdx.x;
    if (i < B_*(N_-1)) {
        g_glb[i] = 0.5f * g_glb[i] + 0.5f * g_cls[i];
        g_cls[i] = 0.f;
    }
}

// ---------------- glb output copy ----------------
__global__ void copy_glb_kernel(float* __restrict__ out) {
    int i = blockIdx.x*blockDim.x + threadIdx.x;
    if (i < B_*(N_-1)) out[(size_t)B_*N_*C_ + i] = g_glb[i];
}

// ---------------- launch ----------------
extern "C" void kernel_launch(void* const* d_in, const int* in_sizes, int n_in,
                              void* d_out, int out_size) {
    const float* x       = (const float*)d_in[0];
    const float* gattn   = (const float*)d_in[1];
    const float* split_w = (const float*)d_in[2];
    const float* split_b = (const float*)d_in[3];
    const float* ln1_g   = (const float*)d_in[4];
    const float* ln1_b   = (const float*)d_in[5];
    const float* qkv_w   = (const float*)d_in[6];
    const float* qkv_b   = (const float*)d_in[7];
    const float* proj_w  = (const float*)d_in[8];
    const float* proj_b  = (const float*)d_in[9];
    const float* ln2_g   = (const float*)d_in[10];
    const float* ln2_b   = (const float*)d_in[11];
    const float* fc1_w   = (const float*)d_in[12];
    const float* fc1_b   = (const float*)d_in[13];
    const float* fc2_w   = (const float*)d_in[14];
    const float* fc2_b   = (const float*)d_in[15];

    float *px, *pcls, *psrow, *ppart;
    __half *ph, *pqkv, *po, *pmlp, *ptok;
    __half *pwsplit, *pwqkv, *pwproj, *pwfc1, *pwfc2;
    cudaGetSymbolAddress((void**)&px,   g_x);
    cudaGetSymbolAddress((void**)&ph,   g_h);
    cudaGetSymbolAddress((void**)&pqkv, g_qkv);
    cudaGetSymbolAddress((void**)&po,   g_o);
    cudaGetSymbolAddress((void**)&pmlp, g_mlp);
    cudaGetSymbolAddress((void**)&ptok, g_tok);
    cudaGetSymbolAddress((void**)&pcls, g_cls);
    cudaGetSymbolAddress((void**)&psrow, g_srow);
    cudaGetSymbolAddress((void**)&ppart, g_part);
    cudaGetSymbolAddress((void**)&pwsplit, g_wsplit);
    cudaGetSymbolAddress((void**)&pwqkv,   g_wqkv);
    cudaGetSymbolAddress((void**)&pwproj,  g_wproj);
    cudaGetSymbolAddress((void**)&pwfc1,   g_wfc1);
    cudaGetSymbolAddress((void**)&pwfc2,   g_wfc2);

    cudaFuncSetAttribute(gemm_h,     cudaFuncAttributeMaxDynamicSharedMemorySize, GEMM_SMEM);
    cudaFuncSetAttribute(flash_attn, cudaFuncAttributeMaxDynamicSharedMemorySize, FA_SMEM);

    wconv5_kernel<<<2048, 256>>>(split_w, pwsplit, SW_SZ,
                                 qkv_w,   pwqkv,   L_*QW_SZ,
                                 proj_w,  pwproj,  L_*PW_SZ,
                                 fc1_w,   pwfc1,   L_*F1_SZ,
                                 fc2_w,   pwfc2,   L_*F2_SZ);
    sort_kernel<<<B_, 256>>>(gattn);
    gather_kernel<<<B_*197, 256>>>(x);
    init_kernel<<<(B_*(N_-1) + 255)/256, 256>>>();

    {   // split GEMM  M=1568, N=3072, K=768
        dim3 grid((4*C_)/128, (B_*SPLN + 127)/128);
        gemm_h<<<grid, 256, GEMM_SMEM>>>(ptok, pwsplit, split_b, nullptr, px,
                                         B_*SPLN, 4*C_, C_, 3);
    }

    for (int l = 0; l < L_; l++) {
        const float* l1g = ln1_g + l*C_;
        const float* l1b = ln1_b + l*C_;
        const __half* qw = pwqkv + (size_t)l*QW_SZ;
        const float* qb  = qkv_b + l*3*C_;
        const __half* pw = pwproj + (size_t)l*PW_SZ;
        const float* pb  = proj_b + l*C_;
        const float* l2g = ln2_g + l*C_;
        const float* l2b = ln2_b + l*C_;
        const __half* w1 = pwfc1 + (size_t)l*F1_SZ;
        const float* b1  = fc1_b + l*HM_;
        const __half* w2 = pwfc2 + (size_t)l*F2_SZ;
        const float* b2  = fc2_b + l*C_;

        // ln1: layer 0 reads plain x; later layers also fold in the previous fc2 partials
        if (l == 0) {
            ln_kernel<<<(M_ROWS + 7)/8, 256>>>(px, ph, l1g, l1b);
        } else {
            const float* b2_prev = fc2_b + (l-1)*C_;
            ln_red_kernel<<<(M_ROWS + 7)/8, 256>>>(ppart, b2_prev, px, ph, l1g, l1b);
        }

        { dim3 grid((3*C_)/128, (M_ROWS + 127)/128);
          gemm_h<<<grid, 256, GEMM_SMEM>>>(ph, qw, qb, nullptr, pqkv, M_ROWS, 3*C_, C_, 4); }

        { dim3 grid(4, B_*H_);
          flash_attn<<<grid, 256, FA_SMEM>>>(pqkv, po, psrow); }

        cls2_kernel<<<B_*H_, 512>>>(psrow, pcls);

        glb_kernel<<<(B_*(N_-1) + 255)/256, 256>>>();

        {   // proj: split-K=2 partials
            dim3 grid(C_/128, (M_ROWS + 127)/128, 2);
            gemm_h<<<grid, 256, GEMM_SMEM>>>(po, pw, nullptr, nullptr, ppart,
                                             M_ROWS, C_, C_, 5);
        }

        // ln2 folds proj partials + bias into x
        ln_red_kernel<<<(M_ROWS + 7)/8, 256>>>(ppart, pb, px, ph, l2g, l2b);

        { dim3 grid(HM_/128, (M_ROWS + 127)/128);
          gemm_h<<<grid, 256, GEMM_SMEM>>>(ph, w1, b1, nullptr, pmlp, M_ROWS, HM_, C_, 1); }

        if (l < L_ - 1) {
            // fc2: split-K=2 partials (reduced by next layer's ln1)
            dim3 grid(C_/128, (M_ROWS + 127)/128, 2);
            gemm_h<<<grid, 256, GEMM_SMEM>>>(pmlp, w2, nullptr, nullptr, ppart,
                                             M_ROWS, C_, HM_, 5);
        } else {
            // final fc2: fused residual write directly into d_out
            dim3 grid(C_/128, (M_ROWS + 127)/128);
            gemm_h<<<grid, 256, GEMM_SMEM>>>(pmlp, w2, b2, px, (float*)d_out,
                                             M_ROWS, C_, HM_, 2);
        }
    }

    copy_glb_kernel<<<(B_*(N_-1) + 255)/256, 256>>>((float*)d_out);
}